// round 13
// baseline (speedup 1.0000x reference)
#include <cuda_runtime.h>
#include <cuda_bf16.h>
#include <cstdint>

// Problem dims
#define B_  64
#define T_  1024
#define D_  256
#define H_  512
#define O_  256
#define MROWS (B_ * T_)   // 65536

// ---------------------------------------------------------------------------
// Scratch (allocation-free per harness rules)
// ---------------------------------------------------------------------------
__device__ float g_xw[(size_t)B_ * T_ * H_];
__device__ float g_x2[(size_t)B_ * T_ * H_];
__device__ __nv_bfloat16 g_ah[(size_t)MROWS * H_];   // A-hi (bf16)
__device__ __nv_bfloat16 g_al[(size_t)MROWS * H_];   // A-lo (bf16 residual)
__device__ __nv_bfloat16 g_wh[(size_t)H_ * H_];      // W-hi
__device__ __nv_bfloat16 g_wl[(size_t)H_ * H_];      // W-lo

// ---------------------------------------------------------------------------
// Helpers
// ---------------------------------------------------------------------------
__device__ __forceinline__ void ffma2(unsigned long long &acc,
                                      unsigned long long a,
                                      unsigned long long b) {
    asm("fma.rn.f32x2 %0, %1, %2, %0;" : "+l"(acc) : "l"(a), "l"(b));
}
__device__ __forceinline__ float lo32(unsigned long long u) {
    return __uint_as_float((unsigned)(u & 0xffffffffull));
}
__device__ __forceinline__ float hi32(unsigned long long u) {
    return __uint_as_float((unsigned)(u >> 32));
}
__device__ __forceinline__ float tanh_acc(float x) {
    float a = fabsf(x);
    float e = __expf(-2.0f * a);
    float r = (1.0f - e) / (1.0f + e);
    return (x < 0.0f) ? -r : r;
}
__device__ __forceinline__ uint32_t smem_u32(const void* p) {
    uint32_t a;
    asm("{ .reg .u64 t; cvta.to.shared.u64 t, %1; cvt.u32.u64 %0, t; }"
        : "=r"(a) : "l"(p));
    return a;
}

// ---- mbarrier / DSMEM primitives (scan) ----
__device__ __forceinline__ void mbar_init(uint32_t addr, uint32_t count) {
    asm volatile("mbarrier.init.shared.b64 [%0], %1;" :: "r"(addr), "r"(count) : "memory");
}
__device__ __forceinline__ void mbar_arrive_expect_tx(uint32_t addr, uint32_t bytes) {
    asm volatile("mbarrier.arrive.expect_tx.shared.b64 _, [%0], %1;"
                 :: "r"(addr), "r"(bytes) : "memory");
}
__device__ __forceinline__ void mbar_wait(uint32_t addr, uint32_t parity) {
    asm volatile(
        "{\n\t"
        ".reg .pred P;\n\t"
        "WL_%=:\n\t"
        "mbarrier.try_wait.parity.acquire.cta.shared::cta.b64 P, [%0], %1, 0x989680;\n\t"
        "@!P bra WL_%=;\n\t"
        "}"
        :: "r"(addr), "r"(parity) : "memory");
}
__device__ __forceinline__ void st_async_v4(uint32_t dst_local, uint32_t mbar_local,
                                            int rank, uint4 v) {
    uint32_t dst, rmb;
    asm volatile("mapa.shared::cluster.u32 %0, %1, %2;" : "=r"(dst) : "r"(dst_local), "r"(rank));
    asm volatile("mapa.shared::cluster.u32 %0, %1, %2;" : "=r"(rmb) : "r"(mbar_local), "r"(rank));
    asm volatile(
        "st.async.shared::cluster.mbarrier::complete_tx::bytes.v4.b32 "
        "[%0], {%1, %2, %3, %4}, [%5];"
        :: "r"(dst), "r"(v.x), "r"(v.y), "r"(v.z), "r"(v.w), "r"(rmb) : "memory");
}
__device__ __forceinline__ void cluster_sync() {
    asm volatile("barrier.cluster.arrive.aligned;" ::: "memory");
    asm volatile("barrier.cluster.wait.aligned;"   ::: "memory");
}

// ---- ldmatrix / mma.sync (sm_80-era PTX; legal on compute_103) ----
__device__ __forceinline__ void ldsm_x4(uint32_t &r0, uint32_t &r1,
                                        uint32_t &r2, uint32_t &r3, uint32_t addr) {
    asm volatile("ldmatrix.sync.aligned.m8n8.x4.shared.b16 {%0,%1,%2,%3}, [%4];"
                 : "=r"(r0), "=r"(r1), "=r"(r2), "=r"(r3) : "r"(addr));
}
__device__ __forceinline__ void ldsm_x2(uint32_t &r0, uint32_t &r1, uint32_t addr) {
    asm volatile("ldmatrix.sync.aligned.m8n8.x2.shared.b16 {%0,%1}, [%2];"
                 : "=r"(r0), "=r"(r1) : "r"(addr));
}
__device__ __forceinline__ void mma16816(float &d0, float &d1, float &d2, float &d3,
                                         uint32_t a0, uint32_t a1, uint32_t a2, uint32_t a3,
                                         uint32_t b0, uint32_t b1) {
    asm volatile(
        "mma.sync.aligned.m16n8k16.row.col.f32.bf16.bf16.f32 "
        "{%0,%1,%2,%3}, {%4,%5,%6,%7}, {%8,%9}, {%0,%1,%2,%3};"
        : "+f"(d0), "+f"(d1), "+f"(d2), "+f"(d3)
        : "r"(a0), "r"(a1), "r"(a2), "r"(a3), "r"(b0), "r"(b1));
}

// ---------------------------------------------------------------------------
// fp32 -> (bf16 hi, bf16 lo) split conversion, 4 elems/thread.
// ---------------------------------------------------------------------------
__global__ __launch_bounds__(256)
void conv_split(const float* __restrict__ src,
                __nv_bfloat16* __restrict__ hi,
                __nv_bfloat16* __restrict__ lo)
{
    size_t i = ((size_t)blockIdx.x * 256 + threadIdx.x) * 4;
    float4 v = *reinterpret_cast<const float4*>(src + i);
    __nv_bfloat16 h0 = __float2bfloat16(v.x), h1 = __float2bfloat16(v.y);
    __nv_bfloat16 h2 = __float2bfloat16(v.z), h3 = __float2bfloat16(v.w);
    __nv_bfloat16 l0 = __float2bfloat16(v.x - __bfloat162float(h0));
    __nv_bfloat16 l1 = __float2bfloat16(v.y - __bfloat162float(h1));
    __nv_bfloat16 l2 = __float2bfloat16(v.z - __bfloat162float(h2));
    __nv_bfloat16 l3 = __float2bfloat16(v.w - __bfloat162float(h3));
    __nv_bfloat162 hp0(h0, h1), hp1(h2, h3), lp0(l0, l1), lp1(l2, l3);
    *reinterpret_cast<uint2*>(hi + i) =
        make_uint2(*reinterpret_cast<uint32_t*>(&hp0), *reinterpret_cast<uint32_t*>(&hp1));
    *reinterpret_cast<uint2*>(lo + i) =
        make_uint2(*reinterpret_cast<uint32_t*>(&lp0), *reinterpret_cast<uint32_t*>(&lp1));
}

// ---------------------------------------------------------------------------
// HMMA GEMM (unchanged from R12): C = A @ W^T + bias1 + bias2, fp32-split.
// ---------------------------------------------------------------------------
template <int K>
__global__ __launch_bounds__(256)
void mma_gemm(const __nv_bfloat16* __restrict__ Ah,
              const __nv_bfloat16* __restrict__ Al,
              const __nv_bfloat16* __restrict__ Wh,
              const __nv_bfloat16* __restrict__ Wl,
              const float* __restrict__ bias1,
              const float* __restrict__ bias2,
              float* __restrict__ C)
{
    __shared__ alignas(1024) unsigned char smA[16384];
    __shared__ alignas(1024) unsigned char smB[16384];

    const int tid  = threadIdx.x;
    const int wid  = tid >> 5;
    const int lane = tid & 31;
    const int m0   = blockIdx.x * 128;
    const int n0   = blockIdx.y * 128;
    const int wm0  = (wid >> 2) * 64;
    const int wn0  = (wid & 3) * 32;

    const uint32_t a_s = smem_u32(smA), b_s = smem_u32(smB);
    const int rowA = lane & 15;
    const int kA8  = (lane & 16) ? 16 : 0;
    const uint32_t xorA = (uint32_t)(rowA & 7) << 4;
    const uint32_t baseA = (uint32_t)(wm0 + rowA) * 128 + kA8;
    const int rowB = lane & 7;
    const int kB8  = (lane & 8) ? 16 : 0;
    const uint32_t xorB = (uint32_t)(rowB & 7) << 4;
    const uint32_t baseB = (uint32_t)(wn0 + rowB) * 128 + kB8;

    float acc[4][4][4];
#pragma unroll
    for (int f = 0; f < 4; f++)
#pragma unroll
        for (int g = 0; g < 4; g++)
#pragma unroll
            for (int e = 0; e < 4; e++) acc[f][g][e] = 0.0f;

    constexpr int CH  = K / 64;
    constexpr int NIT = 3 * CH;

    for (int it = 0; it < NIT; it++) {
        const int p  = it / CH;
        const int kc = it % CH;
        const __nv_bfloat16* As = (p == 1) ? Al : Ah;
        const __nv_bfloat16* Bs = (p == 2) ? Wl : Wh;

        uint4 va[4], vb[4];
#pragma unroll
        for (int i = 0; i < 4; i++) {
            int s   = tid + 256 * i;
            int row = s >> 3, seg = s & 7;
            va[i] = *reinterpret_cast<const uint4*>(
                As + (size_t)(m0 + row) * K + kc * 64 + seg * 8);
            vb[i] = *reinterpret_cast<const uint4*>(
                Bs + (size_t)(n0 + row) * K + kc * 64 + seg * 8);
        }
        __syncthreads();
#pragma unroll
        for (int i = 0; i < 4; i++) {
            int s   = tid + 256 * i;
            int row = s >> 3, seg = s & 7;
            uint32_t off = (uint32_t)(row * 128 + seg * 16);
            off ^= ((off >> 3) & 0x70);
            *reinterpret_cast<uint4*>(smA + off) = va[i];
            *reinterpret_cast<uint4*>(smB + off) = vb[i];
        }
        __syncthreads();

#pragma unroll
        for (int ks = 0; ks < 4; ks++) {
            uint32_t af[4][4], bf[4][2];
#pragma unroll
            for (int f = 0; f < 4; f++) {
                uint32_t addr = a_s + (((baseA + (uint32_t)(f * 2048 + ks * 32)) ^ xorA));
                ldsm_x4(af[f][0], af[f][1], af[f][2], af[f][3], addr);
            }
#pragma unroll
            for (int g = 0; g < 4; g++) {
                uint32_t addr = b_s + (((baseB + (uint32_t)(g * 1024 + ks * 32)) ^ xorB));
                ldsm_x2(bf[g][0], bf[g][1], addr);
            }
#pragma unroll
            for (int f = 0; f < 4; f++)
#pragma unroll
                for (int g = 0; g < 4; g++)
                    mma16816(acc[f][g][0], acc[f][g][1], acc[f][g][2], acc[f][g][3],
                             af[f][0], af[f][1], af[f][2], af[f][3],
                             bf[g][0], bf[g][1]);
        }
    }

    const int r  = lane >> 2;
    const int c4 = lane & 3;
#pragma unroll
    for (int g = 0; g < 4; g++) {
        const int n = n0 + wn0 + g * 8 + c4 * 2;
        float2 bsum;
        bsum.x = bias1[n]     + bias2[n];
        bsum.y = bias1[n + 1] + bias2[n + 1];
#pragma unroll
        for (int f = 0; f < 4; f++) {
            const int mr = m0 + wm0 + f * 16 + r;
            float2 v0, v1;
            v0.x = acc[f][g][0] + bsum.x; v0.y = acc[f][g][1] + bsum.y;
            v1.x = acc[f][g][2] + bsum.x; v1.y = acc[f][g][3] + bsum.y;
            *reinterpret_cast<float2*>(C + (size_t)mr * H_ + n)       = v0;
            *reinterpret_cast<float2*>(C + (size_t)(mr + 8) * H_ + n) = v1;
        }
    }
}

// ---------------------------------------------------------------------------
// Recurrent scan, R13: intra-CTA barrier-free step.
//
// 8-CTA cluster, 4 chains. CTA rank owns j in [rank*64, +64). 512 threads:
// thread (warp w, lane = jj*16 + ks) owns rows j = 4w+2jj, 4w+2jj+1 over
// k-chunk [ks*32, +32) for all 4 chains (128 FFMA2, W 64 regs — as R10).
//
// Reduction: 4 shfl.bfly rounds over the 16 ks lanes (no smem, no barrier).
// Lanes ks<4 (chain c=ks) add xW, apply tanh, and STG h when needed. Four
// shfl.idx assemble each v4 message (4 consecutive j of one chain) in
// registers; every lane ships exactly ONE st.async.v4 to rank
// (ks>>2)|(jj<<2) — including SELF, so the local slice also arrives via the
// mbarrier and NO __syncthreads exists anywhere in the loop. expect_tx =
// 8*1024. hs layout is k-chunk-major with stride-36 padding:
// hs[buf][(c*16 + kchunk)*36 + i], kchunk = global k/32 (source rank
// interleaved), giving >=2-phase-bounded LDS conflicts.
//
// Double-buffer safety (no barriers needed): a peer publishes step t+1 only
// after consuming step t, which requires OUR step-t message, sent after our
// step-t reads of hs[(t-1)&1] — so arrivals for t+1 never race our reads.
// ---------------------------------------------------------------------------
template <bool WRITE_ALL>
__global__ __launch_bounds__(512, 1) __cluster_dims__(8, 1, 1)
void scan_kernel(float* __restrict__ xw, const float* __restrict__ Whh)
{
    __shared__ alignas(16) float hs[2][4 * 16 * 36];   // 2 x 9216 B
    __shared__ alignas(8) unsigned long long mbar[2];

    const int tid  = threadIdx.x;
    const int lane = tid & 31;
    const int w    = tid >> 5;          // warp 0..15 -> j group 4w..4w+3
    const int ks   = lane & 15;         // k-chunk
    const int jj   = lane >> 4;         // row-pair select
    const int rank = blockIdx.x & 7;
    const int cb   = (blockIdx.x >> 3) * 4;
    const int c4   = ks & 3;            // publish chain / tanh chain (ks<4)
    const int rdst = (ks >> 2) | (jj << 2);   // publish destination rank

    // W rows j0 = 4w+2jj, j0+1 over k in [ks*32, +32) -> 64 regs.
    const int j0l = 4 * w + 2 * jj;
    ulonglong2 W0[8], W1[8];
    {
        const ulonglong2* p0 = reinterpret_cast<const ulonglong2*>(
            Whh + (size_t)(rank * 64 + j0l) * H_ + ks * 32);
        const ulonglong2* p1 = reinterpret_cast<const ulonglong2*>(
            Whh + (size_t)(rank * 64 + j0l + 1) * H_ + ks * 32);
#pragma unroll
        for (int i = 0; i < 8; i++) { W0[i] = p0[i]; W1[i] = p1[i]; }
    }

    const uint32_t mb0 = smem_u32(&mbar[0]);
    const uint32_t mb1 = smem_u32(&mbar[1]);
    const uint32_t hsb = smem_u32(&hs[0][0]);
    constexpr uint32_t HS_BUFB = 4 * 16 * 36 * 4;   // 9216 B per buffer

    // Publish destination offset (identical in every CTA): values are
    // h[c4][j = rank*64 + 4w .. +3] -> k-chunk 2*rank + (w>=8), word (4w)&31.
    const uint32_t dstoff =
        ((uint32_t)(c4 * 16 + 2 * rank + (w >> 3)) * 36 + ((uint32_t)(4 * w) & 31)) * 4u;

    // tanh lanes (ks<4, chain = ks): global row pointer for xW / h.
    const bool tl = (ks < 4);
    float* own = xw + (size_t)(cb + c4) * T_ * H_ + rank * 64 + j0l;

    if (tid == 0) {
        mbar_init(mb0, 1);
        mbar_init(mb1, 1);
        mbar_arrive_expect_tx(mb0, 8192);   // step 0 (8 slices incl. self)
        mbar_arrive_expect_tx(mb1, 8192);   // step 1
    }
    __syncthreads();
    cluster_sync();                          // mbarriers live before any tx

    for (int t = 0; t < T_; t++) {
        // Prefetch xW(t) (independent of h(t-1)); tanh lanes only.
        float2 xwv = make_float2(0.0f, 0.0f);
        if (tl) xwv = *reinterpret_cast<const float2*>(own + (size_t)t * H_);

        float sA0 = 0.f, sA1 = 0.f, sB0 = 0.f, sB1 = 0.f;
        float sC0 = 0.f, sC1 = 0.f, sD0 = 0.f, sD1 = 0.f;

        if (t > 0) {
            const int s = t - 1;
            const uint32_t mb = (s & 1) ? mb1 : mb0;
            mbar_wait(mb, (uint32_t)((s >> 1) & 1));
            if (tid == 0 && t <= T_ - 3) mbar_arrive_expect_tx(mb, 8192);

            const float* hb = hs[s & 1];
            const ulonglong2* h0 = reinterpret_cast<const ulonglong2*>(hb + (0 * 16 + ks) * 36);
            const ulonglong2* h1 = reinterpret_cast<const ulonglong2*>(hb + (1 * 16 + ks) * 36);
            const ulonglong2* h2 = reinterpret_cast<const ulonglong2*>(hb + (2 * 16 + ks) * 36);
            const ulonglong2* h3 = reinterpret_cast<const ulonglong2*>(hb + (3 * 16 + ks) * 36);

            unsigned long long aA0 = 0ull, aA1 = 0ull, aB0 = 0ull, aB1 = 0ull;
            unsigned long long aC0 = 0ull, aC1 = 0ull, aD0 = 0ull, aD1 = 0ull;
#pragma unroll
            for (int i = 0; i < 8; i++) {
                ulonglong2 w0 = W0[i], w1 = W1[i];
                ulonglong2 v0 = h0[i];
                ffma2(aA0, v0.x, w0.x); ffma2(aA0, v0.y, w0.y);
                ffma2(aA1, v0.x, w1.x); ffma2(aA1, v0.y, w1.y);
                ulonglong2 v1 = h1[i];
                ffma2(aB0, v1.x, w0.x); ffma2(aB0, v1.y, w0.y);
                ffma2(aB1, v1.x, w1.x); ffma2(aB1, v1.y, w1.y);
                ulonglong2 v2 = h2[i];
                ffma2(aC0, v2.x, w0.x); ffma2(aC0, v2.y, w0.y);
                ffma2(aC1, v2.x, w1.x); ffma2(aC1, v2.y, w1.y);
                ulonglong2 v3 = h3[i];
                ffma2(aD0, v3.x, w0.x); ffma2(aD0, v3.y, w0.y);
                ffma2(aD1, v3.x, w1.x); ffma2(aD1, v3.y, w1.y);
            }
            sA0 = lo32(aA0) + hi32(aA0); sA1 = lo32(aA1) + hi32(aA1);
            sB0 = lo32(aB0) + hi32(aB0); sB1 = lo32(aB1) + hi32(aB1);
            sC0 = lo32(aC0) + hi32(aC0); sC1 = lo32(aC1) + hi32(aC1);
            sD0 = lo32(aD0) + hi32(aD0); sD1 = lo32(aD1) + hi32(aD1);

            // 4 bfly rounds over the 16 ks lanes (stays within ks nibble).
#pragma unroll
            for (int d = 1; d <= 8; d <<= 1) {
                sA0 += __shfl_xor_sync(0xffffffffu, sA0, d);
                sA1 += __shfl_xor_sync(0xffffffffu, sA1, d);
                sB0 += __shfl_xor_sync(0xffffffffu, sB0, d);
                sB1 += __shfl_xor_sync(0xffffffffu, sB1, d);
                sC0 += __shfl_xor_sync(0xffffffffu, sC0, d);
                sC1 += __shfl_xor_sync(0xffffffffu, sC1, d);
                sD0 += __shfl_xor_sync(0xffffffffu, sD0, d);
                sD1 += __shfl_xor_sync(0xffffffffu, sD1, d);
            }
        }

        // tanh on designated lanes (chain = ks < 4); select by runtime ks.
        float v0 = 0.0f, v1 = 0.0f;
        if (tl) {
            float p0 = (ks & 2) ? ((ks & 1) ? sD0 : sC0) : ((ks & 1) ? sB0 : sA0);
            float p1 = (ks & 2) ? ((ks & 1) ? sD1 : sC1) : ((ks & 1) ? sB1 : sA1);
            v0 = tanh_acc(p0 + xwv.x);
            v1 = tanh_acc(p1 + xwv.y);
            if (WRITE_ALL || t == T_ - 1) {
                *reinterpret_cast<float2*>(own + (size_t)t * H_) = make_float2(v0, v1);
            }
        }

        if (t <= T_ - 2) {
            // Assemble v4 (chain c4, j = 4w..4w+3) from lanes c4 and 16+c4.
            float tv0 = __shfl_sync(0xffffffffu, v0, c4);
            float tv1 = __shfl_sync(0xffffffffu, v1, c4);
            float tv2 = __shfl_sync(0xffffffffu, v0, 16 + c4);
            float tv3 = __shfl_sync(0xffffffffu, v1, 16 + c4);
            uint4 msg = make_uint4(__float_as_uint(tv0), __float_as_uint(tv1),
                                   __float_as_uint(tv2), __float_as_uint(tv3));
            const uint32_t boff = (t & 1) ? HS_BUFB : 0u;
            st_async_v4(hsb + boff + dstoff, (t & 1) ? mb1 : mb0, rdst, msg);
        }
    }

    cluster_sync();   // all inbound stores retired before smem dies
}

// ---------------------------------------------------------------------------
// FC: out[b][o] = h1_final[b] . W_fc[o] + b_fc[o]
// ---------------------------------------------------------------------------
__global__ __launch_bounds__(256)
void fc_kernel(const float* __restrict__ hsrc,
               const float* __restrict__ Wfc,
               const float* __restrict__ bfc,
               float* __restrict__ out)
{
    __shared__ float hb[H_];
    const int b = blockIdx.x;
    const int o = threadIdx.x;
    for (int i = o; i < H_; i += 256)
        hb[i] = hsrc[((size_t)b * T_ + (T_ - 1)) * H_ + i];
    __syncthreads();

    const float4* w = reinterpret_cast<const float4*>(Wfc + (size_t)o * H_);
    float acc = 0.0f;
#pragma unroll 8
    for (int i = 0; i < H_ / 4; i++) {
        float4 wv = w[i];
        acc += hb[4 * i + 0] * wv.x + hb[4 * i + 1] * wv.y
             + hb[4 * i + 2] * wv.z + hb[4 * i + 3] * wv.w;
    }
    out[(size_t)b * O_ + o] = acc + bfc[o];
}

// ---------------------------------------------------------------------------
// kernel_launch: 9 graph-capturable kernel launches, stream-ordered.
// ---------------------------------------------------------------------------
extern "C" void kernel_launch(void* const* d_in, const int* in_sizes, int n_in,
                              void* d_out, int out_size)
{
    (void)in_sizes; (void)n_in; (void)out_size;
    const float* x    = (const float*)d_in[0];
    const float* Wih0 = (const float*)d_in[1];
    const float* Whh0 = (const float*)d_in[2];
    const float* bih0 = (const float*)d_in[3];
    const float* bhh0 = (const float*)d_in[4];
    const float* Wih1 = (const float*)d_in[5];
    const float* Whh1 = (const float*)d_in[6];
    const float* bih1 = (const float*)d_in[7];
    const float* bhh1 = (const float*)d_in[8];
    const float* Wfc  = (const float*)d_in[9];
    const float* bfc  = (const float*)d_in[10];

    float *xw = nullptr, *x2 = nullptr;
    __nv_bfloat16 *ah = nullptr, *al = nullptr, *wh = nullptr, *wl = nullptr;
    cudaGetSymbolAddress((void**)&xw, g_xw);
    cudaGetSymbolAddress((void**)&x2, g_x2);
    cudaGetSymbolAddress((void**)&ah, g_ah);
    cudaGetSymbolAddress((void**)&al, g_al);
    cudaGetSymbolAddress((void**)&wh, g_wh);
    cudaGetSymbolAddress((void**)&wl, g_wl);

    dim3 mgrid(MROWS / 128, H_ / 128);   // (512, 4)

    // ---- Layer 0: split-convert, HMMA input projection, scan ----
    conv_split<<<(H_ * D_) / 1024, 256>>>(Wih0, wh, wl);
    conv_split<<<((size_t)MROWS * D_) / 1024, 256>>>(x, ah, al);
    mma_gemm<D_><<<mgrid, 256>>>(ah, al, wh, wl, bih0, bhh0, xw);
    scan_kernel<true><<<128, 512>>>(xw, Whh0);

    // ---- Layer 1 ----
    conv_split<<<(H_ * H_) / 1024, 256>>>(Wih1, wh, wl);
    conv_split<<<((size_t)MROWS * H_) / 1024, 256>>>(xw, ah, al);
    mma_gemm<H_><<<mgrid, 256>>>(ah, al, wh, wl, bih1, bhh1, x2);
    scan_kernel<false><<<128, 512>>>(x2, Whh1);

    // ---- FC on final hidden state of layer 1 ----
    fc_kernel<<<B_, 256>>>(x2, Wfc, bfc, (float*)d_out);
}

// round 14
// speedup vs baseline: 2.3597x; 2.3597x over previous
#include <cuda_runtime.h>
#include <cuda_bf16.h>
#include <cstdint>

// Problem dims
#define B_  64
#define T_  1024
#define D_  256
#define H_  512
#define O_  256
#define MROWS (B_ * T_)   // 65536

// ---------------------------------------------------------------------------
// Scratch (allocation-free per harness rules)
// ---------------------------------------------------------------------------
__device__ float g_xw[(size_t)B_ * T_ * H_];
__device__ float g_x2[(size_t)B_ * T_ * H_];
__device__ __nv_bfloat16 g_ah[(size_t)MROWS * H_];   // A-hi (bf16)
__device__ __nv_bfloat16 g_al[(size_t)MROWS * H_];   // A-lo (bf16 residual)
__device__ __nv_bfloat16 g_wh[(size_t)H_ * H_];      // W-hi
__device__ __nv_bfloat16 g_wl[(size_t)H_ * H_];      // W-lo

// ---------------------------------------------------------------------------
// Helpers
// ---------------------------------------------------------------------------
__device__ __forceinline__ void ffma2(unsigned long long &acc,
                                      unsigned long long a,
                                      unsigned long long b) {
    asm("fma.rn.f32x2 %0, %1, %2, %0;" : "+l"(acc) : "l"(a), "l"(b));
}
__device__ __forceinline__ float lo32(unsigned long long u) {
    return __uint_as_float((unsigned)(u & 0xffffffffull));
}
__device__ __forceinline__ float hi32(unsigned long long u) {
    return __uint_as_float((unsigned)(u >> 32));
}
__device__ __forceinline__ float tanh_acc(float x) {
    float a = fabsf(x);
    float e = __expf(-2.0f * a);
    float r = (1.0f - e) / (1.0f + e);
    return (x < 0.0f) ? -r : r;
}
__device__ __forceinline__ uint32_t smem_u32(const void* p) {
    uint32_t a;
    asm("{ .reg .u64 t; cvta.to.shared.u64 t, %1; cvt.u32.u64 %0, t; }"
        : "=r"(a) : "l"(p));
    return a;
}

// ---- mbarrier / DSMEM primitives (scan) ----
__device__ __forceinline__ void mbar_init(uint32_t addr, uint32_t count) {
    asm volatile("mbarrier.init.shared.b64 [%0], %1;" :: "r"(addr), "r"(count) : "memory");
}
__device__ __forceinline__ void mbar_arrive_expect_tx(uint32_t addr, uint32_t bytes) {
    asm volatile("mbarrier.arrive.expect_tx.shared.b64 _, [%0], %1;"
                 :: "r"(addr), "r"(bytes) : "memory");
}
__device__ __forceinline__ void mbar_wait(uint32_t addr, uint32_t parity) {
    asm volatile(
        "{\n\t"
        ".reg .pred P;\n\t"
        "WL_%=:\n\t"
        "mbarrier.try_wait.parity.acquire.cta.shared::cta.b64 P, [%0], %1, 0x989680;\n\t"
        "@!P bra WL_%=;\n\t"
        "}"
        :: "r"(addr), "r"(parity) : "memory");
}
__device__ __forceinline__ void st_async_v4(uint32_t dst_local, uint32_t mbar_local,
                                            int rank, uint4 v) {
    uint32_t dst, rmb;
    asm volatile("mapa.shared::cluster.u32 %0, %1, %2;" : "=r"(dst) : "r"(dst_local), "r"(rank));
    asm volatile("mapa.shared::cluster.u32 %0, %1, %2;" : "=r"(rmb) : "r"(mbar_local), "r"(rank));
    asm volatile(
        "st.async.shared::cluster.mbarrier::complete_tx::bytes.v4.b32 "
        "[%0], {%1, %2, %3, %4}, [%5];"
        :: "r"(dst), "r"(v.x), "r"(v.y), "r"(v.z), "r"(v.w), "r"(rmb) : "memory");
}
__device__ __forceinline__ void cluster_sync() {
    asm volatile("barrier.cluster.arrive.aligned;" ::: "memory");
    asm volatile("barrier.cluster.wait.aligned;"   ::: "memory");
}

// ---- ldmatrix / mma.sync (sm_80-era PTX; legal on compute_103) ----
__device__ __forceinline__ void ldsm_x4(uint32_t &r0, uint32_t &r1,
                                        uint32_t &r2, uint32_t &r3, uint32_t addr) {
    asm volatile("ldmatrix.sync.aligned.m8n8.x4.shared.b16 {%0,%1,%2,%3}, [%4];"
                 : "=r"(r0), "=r"(r1), "=r"(r2), "=r"(r3) : "r"(addr));
}
__device__ __forceinline__ void ldsm_x2(uint32_t &r0, uint32_t &r1, uint32_t addr) {
    asm volatile("ldmatrix.sync.aligned.m8n8.x2.shared.b16 {%0,%1}, [%2];"
                 : "=r"(r0), "=r"(r1) : "r"(addr));
}
__device__ __forceinline__ void mma16816(float &d0, float &d1, float &d2, float &d3,
                                         uint32_t a0, uint32_t a1, uint32_t a2, uint32_t a3,
                                         uint32_t b0, uint32_t b1) {
    asm volatile(
        "mma.sync.aligned.m16n8k16.row.col.f32.bf16.bf16.f32 "
        "{%0,%1,%2,%3}, {%4,%5,%6,%7}, {%8,%9}, {%0,%1,%2,%3};"
        : "+f"(d0), "+f"(d1), "+f"(d2), "+f"(d3)
        : "r"(a0), "r"(a1), "r"(a2), "r"(a3), "r"(b0), "r"(b1));
}

// ---------------------------------------------------------------------------
// fp32 -> (bf16 hi, bf16 lo) split conversion, 4 elems/thread.
// ---------------------------------------------------------------------------
__global__ __launch_bounds__(256)
void conv_split(const float* __restrict__ src,
                __nv_bfloat16* __restrict__ hi,
                __nv_bfloat16* __restrict__ lo)
{
    size_t i = ((size_t)blockIdx.x * 256 + threadIdx.x) * 4;
    float4 v = *reinterpret_cast<const float4*>(src + i);
    __nv_bfloat16 h0 = __float2bfloat16(v.x), h1 = __float2bfloat16(v.y);
    __nv_bfloat16 h2 = __float2bfloat16(v.z), h3 = __float2bfloat16(v.w);
    __nv_bfloat16 l0 = __float2bfloat16(v.x - __bfloat162float(h0));
    __nv_bfloat16 l1 = __float2bfloat16(v.y - __bfloat162float(h1));
    __nv_bfloat16 l2 = __float2bfloat16(v.z - __bfloat162float(h2));
    __nv_bfloat16 l3 = __float2bfloat16(v.w - __bfloat162float(h3));
    __nv_bfloat162 hp0(h0, h1), hp1(h2, h3), lp0(l0, l1), lp1(l2, l3);
    *reinterpret_cast<uint2*>(hi + i) =
        make_uint2(*reinterpret_cast<uint32_t*>(&hp0), *reinterpret_cast<uint32_t*>(&hp1));
    *reinterpret_cast<uint2*>(lo + i) =
        make_uint2(*reinterpret_cast<uint32_t*>(&lp0), *reinterpret_cast<uint32_t*>(&lp1));
}

// ---------------------------------------------------------------------------
// HMMA GEMM (unchanged from R12): C = A @ W^T + bias1 + bias2, fp32-split.
// ---------------------------------------------------------------------------
template <int K>
__global__ __launch_bounds__(256)
void mma_gemm(const __nv_bfloat16* __restrict__ Ah,
              const __nv_bfloat16* __restrict__ Al,
              const __nv_bfloat16* __restrict__ Wh,
              const __nv_bfloat16* __restrict__ Wl,
              const float* __restrict__ bias1,
              const float* __restrict__ bias2,
              float* __restrict__ C)
{
    __shared__ alignas(1024) unsigned char smA[16384];
    __shared__ alignas(1024) unsigned char smB[16384];

    const int tid  = threadIdx.x;
    const int wid  = tid >> 5;
    const int lane = tid & 31;
    const int m0   = blockIdx.x * 128;
    const int n0   = blockIdx.y * 128;
    const int wm0  = (wid >> 2) * 64;
    const int wn0  = (wid & 3) * 32;

    const uint32_t a_s = smem_u32(smA), b_s = smem_u32(smB);
    const int rowA = lane & 15;
    const int kA8  = (lane & 16) ? 16 : 0;
    const uint32_t xorA = (uint32_t)(rowA & 7) << 4;
    const uint32_t baseA = (uint32_t)(wm0 + rowA) * 128 + kA8;
    const int rowB = lane & 7;
    const int kB8  = (lane & 8) ? 16 : 0;
    const uint32_t xorB = (uint32_t)(rowB & 7) << 4;
    const uint32_t baseB = (uint32_t)(wn0 + rowB) * 128 + kB8;

    float acc[4][4][4];
#pragma unroll
    for (int f = 0; f < 4; f++)
#pragma unroll
        for (int g = 0; g < 4; g++)
#pragma unroll
            for (int e = 0; e < 4; e++) acc[f][g][e] = 0.0f;

    constexpr int CH  = K / 64;
    constexpr int NIT = 3 * CH;

    for (int it = 0; it < NIT; it++) {
        const int p  = it / CH;
        const int kc = it % CH;
        const __nv_bfloat16* As = (p == 1) ? Al : Ah;
        const __nv_bfloat16* Bs = (p == 2) ? Wl : Wh;

        uint4 va[4], vb[4];
#pragma unroll
        for (int i = 0; i < 4; i++) {
            int s   = tid + 256 * i;
            int row = s >> 3, seg = s & 7;
            va[i] = *reinterpret_cast<const uint4*>(
                As + (size_t)(m0 + row) * K + kc * 64 + seg * 8);
            vb[i] = *reinterpret_cast<const uint4*>(
                Bs + (size_t)(n0 + row) * K + kc * 64 + seg * 8);
        }
        __syncthreads();
#pragma unroll
        for (int i = 0; i < 4; i++) {
            int s   = tid + 256 * i;
            int row = s >> 3, seg = s & 7;
            uint32_t off = (uint32_t)(row * 128 + seg * 16);
            off ^= ((off >> 3) & 0x70);
            *reinterpret_cast<uint4*>(smA + off) = va[i];
            *reinterpret_cast<uint4*>(smB + off) = vb[i];
        }
        __syncthreads();

#pragma unroll
        for (int ks = 0; ks < 4; ks++) {
            uint32_t af[4][4], bf[4][2];
#pragma unroll
            for (int f = 0; f < 4; f++) {
                uint32_t addr = a_s + (((baseA + (uint32_t)(f * 2048 + ks * 32)) ^ xorA));
                ldsm_x4(af[f][0], af[f][1], af[f][2], af[f][3], addr);
            }
#pragma unroll
            for (int g = 0; g < 4; g++) {
                uint32_t addr = b_s + (((baseB + (uint32_t)(g * 1024 + ks * 32)) ^ xorB));
                ldsm_x2(bf[g][0], bf[g][1], addr);
            }
#pragma unroll
            for (int f = 0; f < 4; f++)
#pragma unroll
                for (int g = 0; g < 4; g++)
                    mma16816(acc[f][g][0], acc[f][g][1], acc[f][g][2], acc[f][g][3],
                             af[f][0], af[f][1], af[f][2], af[f][3],
                             bf[g][0], bf[g][1]);
        }
    }

    const int r  = lane >> 2;
    const int c4 = lane & 3;
#pragma unroll
    for (int g = 0; g < 4; g++) {
        const int n = n0 + wn0 + g * 8 + c4 * 2;
        float2 bsum;
        bsum.x = bias1[n]     + bias2[n];
        bsum.y = bias1[n + 1] + bias2[n + 1];
#pragma unroll
        for (int f = 0; f < 4; f++) {
            const int mr = m0 + wm0 + f * 16 + r;
            float2 v0, v1;
            v0.x = acc[f][g][0] + bsum.x; v0.y = acc[f][g][1] + bsum.y;
            v1.x = acc[f][g][2] + bsum.x; v1.y = acc[f][g][3] + bsum.y;
            *reinterpret_cast<float2*>(C + (size_t)mr * H_ + n)       = v0;
            *reinterpret_cast<float2*>(C + (size_t)(mr + 8) * H_ + n) = v1;
        }
    }
}

// ---------------------------------------------------------------------------
// Recurrent scan — R12 structure (one compute barrier kept!) with:
//  * publish via in-warp shfl assembly + st.async to ALL 8 ranks (self
//    included) -> no hs staging write, no second __syncthreads.
//  * MODE 0 (layer 0): h written to global as split bf16 (ah/al) directly,
//    fusing conv_split; MODE 1 (layer 1): only t = T-1 written as fp32.
//
// Thread map identical to R12: 512 threads, thread (jp=tid&31, ks=tid>>5)
// computes rows j = 2jp, 2jp+1 over k-chunk [ks*32,+32) for 4 chains;
// producers tid<256 own element (chain tid>>6, j tid&63).
//
// Publish: producer warp w holds 32 consecutive j of chain c = w>>1.
// Lane assembles msg (lane&7) = values of lanes 4(lane&7)..+3 via shfl.idx,
// sends it to ranks (lane>>3) and (lane>>3)+4. 512 sends/CTA/step,
// expect_tx = 8192. Double-buffer safety as R12 (publish of t+1 globally
// gated on consumption of t).
// ---------------------------------------------------------------------------
template <int MODE>
__global__ __launch_bounds__(512, 1) __cluster_dims__(8, 1, 1)
void scan_kernel(float* __restrict__ xw, const float* __restrict__ Whh,
                 __nv_bfloat16* __restrict__ ah, __nv_bfloat16* __restrict__ al)
{
    __shared__ alignas(16) float hs[2][8 * 256];
    __shared__ alignas(16) float red[16][260];
    __shared__ alignas(8) unsigned long long mbar[2];

    const int tid  = threadIdx.x;
    const int lane = tid & 31;
    const int rank = blockIdx.x & 7;
    const int cb   = (blockIdx.x >> 3) * 4;
    const int jp   = tid & 31;
    const int ks   = tid >> 5;
    const int jg0  = rank * 64 + jp * 2;
    const int k0   = ks * 32;

    ulonglong2 Wa[8], Wb[8];
    {
        const ulonglong2* w0 =
            reinterpret_cast<const ulonglong2*>(Whh + (size_t)jg0 * H_ + k0);
        const ulonglong2* w1 =
            reinterpret_cast<const ulonglong2*>(Whh + (size_t)(jg0 + 1) * H_ + k0);
#pragma unroll
        for (int i = 0; i < 8; i++) { Wa[i] = w0[i]; Wb[i] = w1[i]; }
    }

    const int oc = (tid >> 6) & 3;          // producer chain
    const int oj = tid & 63;                // producer j within slice
    const bool is_prod = (tid < 256);
    const size_t own_idx = ((size_t)(cb + oc) * T_ + 0) * H_ + rank * 64 + oj;
    float* own = xw + own_idx;

    const uint32_t mb0  = smem_u32(&mbar[0]);
    const uint32_t mb1  = smem_u32(&mbar[1]);
    const uint32_t hsb  = smem_u32(&hs[0][0]);
    constexpr uint32_t HS_BUFB = 8 * 256 * 4;

    // Publish constants: msg q = lane&7 (j-group), dest ranks lane>>3, +4.
    const int mq   = lane & 7;
    const int rA   = lane >> 3;             // 0..3
    const int rB   = rA + 4;
    const int wvsl = (tid >> 5) & 1;        // which 32-j half of the chain
    const uint32_t dstoff =
        (uint32_t)(rank * 256 + oc * 64 + wvsl * 32 + mq * 4) * 4u;

    if (tid == 0) {
        mbar_init(mb0, 1);
        mbar_init(mb1, 1);
        mbar_arrive_expect_tx(mb0, 8192);
        mbar_arrive_expect_tx(mb1, 8192);
    }
    __syncthreads();
    cluster_sync();

    const int hoff = (ks >> 1) * 256 + (ks & 1) * 32;

    // ---- t = 0 ----
    {
        float v = 0.0f;
        if (is_prod) {
            v = tanh_acc(own[0]);
            if (MODE == 0) {
                __nv_bfloat16 hv = __float2bfloat16(v);
                ah[own_idx] = hv;
                al[own_idx] = __float2bfloat16(v - __bfloat162float(hv));
            }
        }
        if (is_prod) {
            float m0v = __shfl_sync(0xffffffffu, v, mq * 4 + 0);
            float m1v = __shfl_sync(0xffffffffu, v, mq * 4 + 1);
            float m2v = __shfl_sync(0xffffffffu, v, mq * 4 + 2);
            float m3v = __shfl_sync(0xffffffffu, v, mq * 4 + 3);
            uint4 msg = make_uint4(__float_as_uint(m0v), __float_as_uint(m1v),
                                   __float_as_uint(m2v), __float_as_uint(m3v));
            st_async_v4(hsb + dstoff, mb0, rA, msg);
            st_async_v4(hsb + dstoff, mb0, rB, msg);
        }
    }

    for (int t = 1; t < T_; t++) {
        float xwt = is_prod ? own[(size_t)t * H_] : 0.0f;

        const int s = t - 1;
        const int b = s & 1;
        const uint32_t mb = b ? mb1 : mb0;
        mbar_wait(mb, (uint32_t)((s >> 1) & 1));
        if (tid == 0 && t <= T_ - 3) mbar_arrive_expect_tx(mb, 8192);

        const float* hb = hs[b] + hoff;
        const ulonglong2* p0 = reinterpret_cast<const ulonglong2*>(hb + 0 * 64);
        const ulonglong2* p1 = reinterpret_cast<const ulonglong2*>(hb + 1 * 64);
        const ulonglong2* p2 = reinterpret_cast<const ulonglong2*>(hb + 2 * 64);
        const ulonglong2* p3 = reinterpret_cast<const ulonglong2*>(hb + 3 * 64);

        unsigned long long a00 = 0ull, a01 = 0ull;
        unsigned long long a10 = 0ull, a11 = 0ull;
        unsigned long long a20 = 0ull, a21 = 0ull;
        unsigned long long a30 = 0ull, a31 = 0ull;
#pragma unroll
        for (int i = 0; i < 8; i++) {
            ulonglong2 w0 = Wa[i], w1 = Wb[i];
            ulonglong2 v0 = p0[i];
            ffma2(a00, v0.x, w0.x); ffma2(a00, v0.y, w0.y);
            ffma2(a01, v0.x, w1.x); ffma2(a01, v0.y, w1.y);
            ulonglong2 v1 = p1[i];
            ffma2(a10, v1.x, w0.x); ffma2(a10, v1.y, w0.y);
            ffma2(a11, v1.x, w1.x); ffma2(a11, v1.y, w1.y);
            ulonglong2 v2 = p2[i];
            ffma2(a20, v2.x, w0.x); ffma2(a20, v2.y, w0.y);
            ffma2(a21, v2.x, w1.x); ffma2(a21, v2.y, w1.y);
            ulonglong2 v3 = p3[i];
            ffma2(a30, v3.x, w0.x); ffma2(a30, v3.y, w0.y);
            ffma2(a31, v3.x, w1.x); ffma2(a31, v3.y, w1.y);
        }
        {
            const int j0 = jp * 2, j1 = jp * 2 + 1;
            red[ks][0 * 64 + j0] = lo32(a00) + hi32(a00);
            red[ks][0 * 64 + j1] = lo32(a01) + hi32(a01);
            red[ks][1 * 64 + j0] = lo32(a10) + hi32(a10);
            red[ks][1 * 64 + j1] = lo32(a11) + hi32(a11);
            red[ks][2 * 64 + j0] = lo32(a20) + hi32(a20);
            red[ks][2 * 64 + j1] = lo32(a21) + hi32(a21);
            red[ks][3 * 64 + j0] = lo32(a30) + hi32(a30);
            red[ks][3 * 64 + j1] = lo32(a31) + hi32(a31);
        }
        __syncthreads();   // the one remaining per-step barrier

        float v = 0.0f;
        if (is_prod) {
            float s0 = red[0][tid]  + red[1][tid]  + red[2][tid]  + red[3][tid];
            float s1 = red[4][tid]  + red[5][tid]  + red[6][tid]  + red[7][tid];
            float s2 = red[8][tid]  + red[9][tid]  + red[10][tid] + red[11][tid];
            float s3 = red[12][tid] + red[13][tid] + red[14][tid] + red[15][tid];
            v = tanh_acc(((s0 + s1) + (s2 + s3)) + xwt);

            if (MODE == 0) {
                const size_t gi = own_idx + (size_t)t * H_;
                __nv_bfloat16 hv = __float2bfloat16(v);
                ah[gi] = hv;
                al[gi] = __float2bfloat16(v - __bfloat162float(hv));
            } else if (t == T_ - 1) {
                own[(size_t)t * H_] = v;
            }

            if (t <= T_ - 2) {
                // In-warp message assembly + direct publish (no staging/sync).
                float m0v = __shfl_sync(0xffffffffu, v, mq * 4 + 0);
                float m1v = __shfl_sync(0xffffffffu, v, mq * 4 + 1);
                float m2v = __shfl_sync(0xffffffffu, v, mq * 4 + 2);
                float m3v = __shfl_sync(0xffffffffu, v, mq * 4 + 3);
                uint4 msg = make_uint4(__float_as_uint(m0v), __float_as_uint(m1v),
                                       __float_as_uint(m2v), __float_as_uint(m3v));
                const uint32_t boff = (t & 1) ? HS_BUFB : 0u;
                const uint32_t pmb  = (t & 1) ? mb1 : mb0;
                st_async_v4(hsb + boff + dstoff, pmb, rA, msg);
                st_async_v4(hsb + boff + dstoff, pmb, rB, msg);
            }
        }
    }

    cluster_sync();
}

// ---------------------------------------------------------------------------
// FC: out[b][o] = h1_final[b] . W_fc[o] + b_fc[o]
// ---------------------------------------------------------------------------
__global__ __launch_bounds__(256)
void fc_kernel(const float* __restrict__ hsrc,
               const float* __restrict__ Wfc,
               const float* __restrict__ bfc,
               float* __restrict__ out)
{
    __shared__ float hb[H_];
    const int b = blockIdx.x;
    const int o = threadIdx.x;
    for (int i = o; i < H_; i += 256)
        hb[i] = hsrc[((size_t)b * T_ + (T_ - 1)) * H_ + i];
    __syncthreads();

    const float4* w = reinterpret_cast<const float4*>(Wfc + (size_t)o * H_);
    float acc = 0.0f;
#pragma unroll 8
    for (int i = 0; i < H_ / 4; i++) {
        float4 wv = w[i];
        acc += hb[4 * i + 0] * wv.x + hb[4 * i + 1] * wv.y
             + hb[4 * i + 2] * wv.z + hb[4 * i + 3] * wv.w;
    }
    out[(size_t)b * O_ + o] = acc + bfc[o];
}

// ---------------------------------------------------------------------------
// kernel_launch: 8 graph-capturable kernel launches, stream-ordered.
// ---------------------------------------------------------------------------
extern "C" void kernel_launch(void* const* d_in, const int* in_sizes, int n_in,
                              void* d_out, int out_size)
{
    (void)in_sizes; (void)n_in; (void)out_size;
    const float* x    = (const float*)d_in[0];
    const float* Wih0 = (const float*)d_in[1];
    const float* Whh0 = (const float*)d_in[2];
    const float* bih0 = (const float*)d_in[3];
    const float* bhh0 = (const float*)d_in[4];
    const float* Wih1 = (const float*)d_in[5];
    const float* Whh1 = (const float*)d_in[6];
    const float* bih1 = (const float*)d_in[7];
    const float* bhh1 = (const float*)d_in[8];
    const float* Wfc  = (const float*)d_in[9];
    const float* bfc  = (const float*)d_in[10];

    float *xw = nullptr, *x2 = nullptr;
    __nv_bfloat16 *ah = nullptr, *al = nullptr, *wh = nullptr, *wl = nullptr;
    cudaGetSymbolAddress((void**)&xw, g_xw);
    cudaGetSymbolAddress((void**)&x2, g_x2);
    cudaGetSymbolAddress((void**)&ah, g_ah);
    cudaGetSymbolAddress((void**)&al, g_al);
    cudaGetSymbolAddress((void**)&wh, g_wh);
    cudaGetSymbolAddress((void**)&wl, g_wl);

    dim3 mgrid(MROWS / 128, H_ / 128);   // (512, 4)

    // ---- Layer 0: split-convert x/W, HMMA input projection, scan (h -> bf16 split, fused) ----
    conv_split<<<(H_ * D_) / 1024, 256>>>(Wih0, wh, wl);
    conv_split<<<((size_t)MROWS * D_) / 1024, 256>>>(x, ah, al);
    mma_gemm<D_><<<mgrid, 256>>>(ah, al, wh, wl, bih0, bhh0, xw);
    scan_kernel<0><<<128, 512>>>(xw, Whh0, ah, al);

    // ---- Layer 1: W convert, HMMA (A = scan0's fused ah/al), scan ----
    conv_split<<<(H_ * H_) / 1024, 256>>>(Wih1, wh, wl);
    mma_gemm<H_><<<mgrid, 256>>>(ah, al, wh, wl, bih1, bhh1, x2);
    scan_kernel<1><<<128, 512>>>(x2, Whh1, ah, al);

    // ---- FC on final hidden state of layer 1 ----
    fc_kernel<<<B_, 256>>>(x2, Wfc, bfc, (float*)d_out);
}

// round 15
// speedup vs baseline: 2.3828x; 1.0098x over previous
#include <cuda_runtime.h>
#include <cuda_bf16.h>
#include <cstdint>

// Problem dims
#define B_  64
#define T_  1024
#define D_  256
#define H_  512
#define O_  256
#define MROWS (B_ * T_)   // 65536

// ---------------------------------------------------------------------------
// Scratch (allocation-free per harness rules)
// ---------------------------------------------------------------------------
__device__ float g_xw[(size_t)B_ * T_ * H_];
__device__ float g_x2[(size_t)B_ * T_ * H_];
__device__ __nv_bfloat16 g_ah[(size_t)MROWS * H_];   // A-hi (bf16)
__device__ __nv_bfloat16 g_al[(size_t)MROWS * H_];   // A-lo (bf16 residual)
__device__ __nv_bfloat16 g_wh[(size_t)H_ * H_];      // W-hi
__device__ __nv_bfloat16 g_wl[(size_t)H_ * H_];      // W-lo

// ---------------------------------------------------------------------------
// Helpers
// ---------------------------------------------------------------------------
__device__ __forceinline__ void ffma2(unsigned long long &acc,
                                      unsigned long long a,
                                      unsigned long long b) {
    asm("fma.rn.f32x2 %0, %1, %2, %0;" : "+l"(acc) : "l"(a), "l"(b));
}
__device__ __forceinline__ float lo32(unsigned long long u) {
    return __uint_as_float((unsigned)(u & 0xffffffffull));
}
__device__ __forceinline__ float hi32(unsigned long long u) {
    return __uint_as_float((unsigned)(u >> 32));
}
__device__ __forceinline__ float tanh_acc(float x) {
    float a = fabsf(x);
    float e = __expf(-2.0f * a);
    float r = (1.0f - e) / (1.0f + e);
    return (x < 0.0f) ? -r : r;
}
__device__ __forceinline__ uint32_t smem_u32(const void* p) {
    uint32_t a;
    asm("{ .reg .u64 t; cvta.to.shared.u64 t, %1; cvt.u32.u64 %0, t; }"
        : "=r"(a) : "l"(p));
    return a;
}

// ---- mbarrier / DSMEM primitives (scan) ----
__device__ __forceinline__ void mbar_init(uint32_t addr, uint32_t count) {
    asm volatile("mbarrier.init.shared.b64 [%0], %1;" :: "r"(addr), "r"(count) : "memory");
}
__device__ __forceinline__ void mbar_arrive_expect_tx(uint32_t addr, uint32_t bytes) {
    asm volatile("mbarrier.arrive.expect_tx.shared.b64 _, [%0], %1;"
                 :: "r"(addr), "r"(bytes) : "memory");
}
__device__ __forceinline__ void mbar_wait(uint32_t addr, uint32_t parity) {
    asm volatile(
        "{\n\t"
        ".reg .pred P;\n\t"
        "WL_%=:\n\t"
        "mbarrier.try_wait.parity.acquire.cta.shared::cta.b64 P, [%0], %1, 0x989680;\n\t"
        "@!P bra WL_%=;\n\t"
        "}"
        :: "r"(addr), "r"(parity) : "memory");
}
__device__ __forceinline__ void st_async_v4(uint32_t dst_local, uint32_t mbar_local,
                                            int rank, uint4 v) {
    uint32_t dst, rmb;
    asm volatile("mapa.shared::cluster.u32 %0, %1, %2;" : "=r"(dst) : "r"(dst_local), "r"(rank));
    asm volatile("mapa.shared::cluster.u32 %0, %1, %2;" : "=r"(rmb) : "r"(mbar_local), "r"(rank));
    asm volatile(
        "st.async.shared::cluster.mbarrier::complete_tx::bytes.v4.b32 "
        "[%0], {%1, %2, %3, %4}, [%5];"
        :: "r"(dst), "r"(v.x), "r"(v.y), "r"(v.z), "r"(v.w), "r"(rmb) : "memory");
}
__device__ __forceinline__ void cluster_sync() {
    asm volatile("barrier.cluster.arrive.aligned;" ::: "memory");
    asm volatile("barrier.cluster.wait.aligned;"   ::: "memory");
}

// ---- ldmatrix / mma.sync (sm_80-era PTX; legal on compute_103) ----
__device__ __forceinline__ void ldsm_x4(uint32_t &r0, uint32_t &r1,
                                        uint32_t &r2, uint32_t &r3, uint32_t addr) {
    asm volatile("ldmatrix.sync.aligned.m8n8.x4.shared.b16 {%0,%1,%2,%3}, [%4];"
                 : "=r"(r0), "=r"(r1), "=r"(r2), "=r"(r3) : "r"(addr));
}
__device__ __forceinline__ void ldsm_x2(uint32_t &r0, uint32_t &r1, uint32_t addr) {
    asm volatile("ldmatrix.sync.aligned.m8n8.x2.shared.b16 {%0,%1}, [%2];"
                 : "=r"(r0), "=r"(r1) : "r"(addr));
}
__device__ __forceinline__ void mma16816(float &d0, float &d1, float &d2, float &d3,
                                         uint32_t a0, uint32_t a1, uint32_t a2, uint32_t a3,
                                         uint32_t b0, uint32_t b1) {
    asm volatile(
        "mma.sync.aligned.m16n8k16.row.col.f32.bf16.bf16.f32 "
        "{%0,%1,%2,%3}, {%4,%5,%6,%7}, {%8,%9}, {%0,%1,%2,%3};"
        : "+f"(d0), "+f"(d1), "+f"(d2), "+f"(d3)
        : "r"(a0), "r"(a1), "r"(a2), "r"(a3), "r"(b0), "r"(b1));
}

// ---------------------------------------------------------------------------
// fp32 -> (bf16 hi, bf16 lo) split conversion, 4 elems/thread.
// ---------------------------------------------------------------------------
__global__ __launch_bounds__(256)
void conv_split(const float* __restrict__ src,
                __nv_bfloat16* __restrict__ hi,
                __nv_bfloat16* __restrict__ lo)
{
    size_t i = ((size_t)blockIdx.x * 256 + threadIdx.x) * 4;
    float4 v = *reinterpret_cast<const float4*>(src + i);
    __nv_bfloat16 h0 = __float2bfloat16(v.x), h1 = __float2bfloat16(v.y);
    __nv_bfloat16 h2 = __float2bfloat16(v.z), h3 = __float2bfloat16(v.w);
    __nv_bfloat16 l0 = __float2bfloat16(v.x - __bfloat162float(h0));
    __nv_bfloat16 l1 = __float2bfloat16(v.y - __bfloat162float(h1));
    __nv_bfloat16 l2 = __float2bfloat16(v.z - __bfloat162float(h2));
    __nv_bfloat16 l3 = __float2bfloat16(v.w - __bfloat162float(h3));
    __nv_bfloat162 hp0(h0, h1), hp1(h2, h3), lp0(l0, l1), lp1(l2, l3);
    *reinterpret_cast<uint2*>(hi + i) =
        make_uint2(*reinterpret_cast<uint32_t*>(&hp0), *reinterpret_cast<uint32_t*>(&hp1));
    *reinterpret_cast<uint2*>(lo + i) =
        make_uint2(*reinterpret_cast<uint32_t*>(&lp0), *reinterpret_cast<uint32_t*>(&lp1));
}

// ---------------------------------------------------------------------------
// HMMA GEMM (unchanged from R12): C = A @ W^T + bias1 + bias2, fp32-split.
// ---------------------------------------------------------------------------
template <int K>
__global__ __launch_bounds__(256)
void mma_gemm(const __nv_bfloat16* __restrict__ Ah,
              const __nv_bfloat16* __restrict__ Al,
              const __nv_bfloat16* __restrict__ Wh,
              const __nv_bfloat16* __restrict__ Wl,
              const float* __restrict__ bias1,
              const float* __restrict__ bias2,
              float* __restrict__ C)
{
    __shared__ alignas(1024) unsigned char smA[16384];
    __shared__ alignas(1024) unsigned char smB[16384];

    const int tid  = threadIdx.x;
    const int wid  = tid >> 5;
    const int lane = tid & 31;
    const int m0   = blockIdx.x * 128;
    const int n0   = blockIdx.y * 128;
    const int wm0  = (wid >> 2) * 64;
    const int wn0  = (wid & 3) * 32;

    const uint32_t a_s = smem_u32(smA), b_s = smem_u32(smB);
    const int rowA = lane & 15;
    const int kA8  = (lane & 16) ? 16 : 0;
    const uint32_t xorA = (uint32_t)(rowA & 7) << 4;
    const uint32_t baseA = (uint32_t)(wm0 + rowA) * 128 + kA8;
    const int rowB = lane & 7;
    const int kB8  = (lane & 8) ? 16 : 0;
    const uint32_t xorB = (uint32_t)(rowB & 7) << 4;
    const uint32_t baseB = (uint32_t)(wn0 + rowB) * 128 + kB8;

    float acc[4][4][4];
#pragma unroll
    for (int f = 0; f < 4; f++)
#pragma unroll
        for (int g = 0; g < 4; g++)
#pragma unroll
            for (int e = 0; e < 4; e++) acc[f][g][e] = 0.0f;

    constexpr int CH  = K / 64;
    constexpr int NIT = 3 * CH;

    for (int it = 0; it < NIT; it++) {
        const int p  = it / CH;
        const int kc = it % CH;
        const __nv_bfloat16* As = (p == 1) ? Al : Ah;
        const __nv_bfloat16* Bs = (p == 2) ? Wl : Wh;

        uint4 va[4], vb[4];
#pragma unroll
        for (int i = 0; i < 4; i++) {
            int s   = tid + 256 * i;
            int row = s >> 3, seg = s & 7;
            va[i] = *reinterpret_cast<const uint4*>(
                As + (size_t)(m0 + row) * K + kc * 64 + seg * 8);
            vb[i] = *reinterpret_cast<const uint4*>(
                Bs + (size_t)(n0 + row) * K + kc * 64 + seg * 8);
        }
        __syncthreads();
#pragma unroll
        for (int i = 0; i < 4; i++) {
            int s   = tid + 256 * i;
            int row = s >> 3, seg = s & 7;
            uint32_t off = (uint32_t)(row * 128 + seg * 16);
            off ^= ((off >> 3) & 0x70);
            *reinterpret_cast<uint4*>(smA + off) = va[i];
            *reinterpret_cast<uint4*>(smB + off) = vb[i];
        }
        __syncthreads();

#pragma unroll
        for (int ks = 0; ks < 4; ks++) {
            uint32_t af[4][4], bf[4][2];
#pragma unroll
            for (int f = 0; f < 4; f++) {
                uint32_t addr = a_s + (((baseA + (uint32_t)(f * 2048 + ks * 32)) ^ xorA));
                ldsm_x4(af[f][0], af[f][1], af[f][2], af[f][3], addr);
            }
#pragma unroll
            for (int g = 0; g < 4; g++) {
                uint32_t addr = b_s + (((baseB + (uint32_t)(g * 1024 + ks * 32)) ^ xorB));
                ldsm_x2(bf[g][0], bf[g][1], addr);
            }
#pragma unroll
            for (int f = 0; f < 4; f++)
#pragma unroll
                for (int g = 0; g < 4; g++)
                    mma16816(acc[f][g][0], acc[f][g][1], acc[f][g][2], acc[f][g][3],
                             af[f][0], af[f][1], af[f][2], af[f][3],
                             bf[g][0], bf[g][1]);
        }
    }

    const int r  = lane >> 2;
    const int c4 = lane & 3;
#pragma unroll
    for (int g = 0; g < 4; g++) {
        const int n = n0 + wn0 + g * 8 + c4 * 2;
        float2 bsum;
        bsum.x = bias1[n]     + bias2[n];
        bsum.y = bias1[n + 1] + bias2[n + 1];
#pragma unroll
        for (int f = 0; f < 4; f++) {
            const int mr = m0 + wm0 + f * 16 + r;
            float2 v0, v1;
            v0.x = acc[f][g][0] + bsum.x; v0.y = acc[f][g][1] + bsum.y;
            v1.x = acc[f][g][2] + bsum.x; v1.y = acc[f][g][3] + bsum.y;
            *reinterpret_cast<float2*>(C + (size_t)mr * H_ + n)       = v0;
            *reinterpret_cast<float2*>(C + (size_t)(mr + 8) * H_ + n) = v1;
        }
    }
}

// ---------------------------------------------------------------------------
// Recurrent scan — EXACT R12 structure (stage -> sync -> 7-peer st.async,
// expect_tx 7168, both per-step barriers). Single change vs R12: the global
// h write. MODE 0 (layer 0): h stored as split bf16 (ah/al) directly,
// fusing the conv_split pass that layer 1's GEMM would otherwise need.
// MODE 1 (layer 1): only t = T-1 written (fp32, for FC).
// ---------------------------------------------------------------------------
template <int MODE>
__global__ __launch_bounds__(512, 1) __cluster_dims__(8, 1, 1)
void scan_kernel(float* __restrict__ xw, const float* __restrict__ Whh,
                 __nv_bfloat16* __restrict__ ah, __nv_bfloat16* __restrict__ al)
{
    __shared__ alignas(16) float hs[2][8 * 256];
    __shared__ alignas(16) float red[16][260];
    __shared__ alignas(8) unsigned long long mbar[2];

    const int tid  = threadIdx.x;
    const int rank = blockIdx.x & 7;
    const int cb   = (blockIdx.x >> 3) * 4;
    const int jp   = tid & 31;
    const int ks   = tid >> 5;
    const int jg0  = rank * 64 + jp * 2;
    const int k0   = ks * 32;

    ulonglong2 Wa[8], Wb[8];
    {
        const ulonglong2* w0 =
            reinterpret_cast<const ulonglong2*>(Whh + (size_t)jg0 * H_ + k0);
        const ulonglong2* w1 =
            reinterpret_cast<const ulonglong2*>(Whh + (size_t)(jg0 + 1) * H_ + k0);
#pragma unroll
        for (int i = 0; i < 8; i++) { Wa[i] = w0[i]; Wb[i] = w1[i]; }
    }

    const int oc = (tid >> 6) & 3;
    const int oj = tid & 63;
    const bool is_prod = (tid < 256);
    const size_t own_idx = ((size_t)(cb + oc) * T_ + 0) * H_ + rank * 64 + oj;
    float* own = xw + own_idx;

    const uint32_t mb0  = smem_u32(&mbar[0]);
    const uint32_t mb1  = smem_u32(&mbar[1]);
    const uint32_t hsd0 = smem_u32(&hs[0][rank * 256]);
    constexpr uint32_t HS_BUFB = 8 * 256 * 4;

    const int rA = (tid >> 6) & 3;
    const int rB = rA + 4;
    const uint32_t sl_off = (uint32_t)(tid & 63) * 16u;

    if (tid == 0) {
        mbar_init(mb0, 1);
        mbar_init(mb1, 1);
        mbar_arrive_expect_tx(mb0, 7168);
        mbar_arrive_expect_tx(mb1, 7168);
    }
    __syncthreads();
    cluster_sync();

    const int hoff = (ks >> 1) * 256 + (ks & 1) * 32;

    // ---- t = 0: h0 = tanh(xw[0]); local slice + publish into buf 0 ----
    {
        if (is_prod) {
            float v = tanh_acc(own[0]);
            if (MODE == 0) {
                __nv_bfloat16 hv = __float2bfloat16(v);
                ah[own_idx] = hv;
                al[own_idx] = __float2bfloat16(v - __bfloat162float(hv));
            }
            hs[0][rank * 256 + tid] = v;
        }
        __syncthreads();
        if (is_prod) {
            uint4 val = *reinterpret_cast<const uint4*>(
                reinterpret_cast<const char*>(&hs[0][rank * 256]) + sl_off);
            if (rA != rank) st_async_v4(hsd0 + sl_off, mb0, rA, val);
            if (rB != rank) st_async_v4(hsd0 + sl_off, mb0, rB, val);
        }
    }

    for (int t = 1; t < T_; t++) {
        float xwt = is_prod ? own[(size_t)t * H_] : 0.0f;

        const int s = t - 1;
        const int b = s & 1;
        const uint32_t mb = b ? mb1 : mb0;
        mbar_wait(mb, (uint32_t)((s >> 1) & 1));
        if (tid == 0 && t <= T_ - 3) mbar_arrive_expect_tx(mb, 7168);

        const float* hb = hs[b] + hoff;
        const ulonglong2* p0 = reinterpret_cast<const ulonglong2*>(hb + 0 * 64);
        const ulonglong2* p1 = reinterpret_cast<const ulonglong2*>(hb + 1 * 64);
        const ulonglong2* p2 = reinterpret_cast<const ulonglong2*>(hb + 2 * 64);
        const ulonglong2* p3 = reinterpret_cast<const ulonglong2*>(hb + 3 * 64);

        unsigned long long a00 = 0ull, a01 = 0ull;
        unsigned long long a10 = 0ull, a11 = 0ull;
        unsigned long long a20 = 0ull, a21 = 0ull;
        unsigned long long a30 = 0ull, a31 = 0ull;
#pragma unroll
        for (int i = 0; i < 8; i++) {
            ulonglong2 w0 = Wa[i], w1 = Wb[i];
            ulonglong2 v0 = p0[i];
            ffma2(a00, v0.x, w0.x); ffma2(a00, v0.y, w0.y);
            ffma2(a01, v0.x, w1.x); ffma2(a01, v0.y, w1.y);
            ulonglong2 v1 = p1[i];
            ffma2(a10, v1.x, w0.x); ffma2(a10, v1.y, w0.y);
            ffma2(a11, v1.x, w1.x); ffma2(a11, v1.y, w1.y);
            ulonglong2 v2 = p2[i];
            ffma2(a20, v2.x, w0.x); ffma2(a20, v2.y, w0.y);
            ffma2(a21, v2.x, w1.x); ffma2(a21, v2.y, w1.y);
            ulonglong2 v3 = p3[i];
            ffma2(a30, v3.x, w0.x); ffma2(a30, v3.y, w0.y);
            ffma2(a31, v3.x, w1.x); ffma2(a31, v3.y, w1.y);
        }
        {
            const int j0 = jp * 2, j1 = jp * 2 + 1;
            red[ks][0 * 64 + j0] = lo32(a00) + hi32(a00);
            red[ks][0 * 64 + j1] = lo32(a01) + hi32(a01);
            red[ks][1 * 64 + j0] = lo32(a10) + hi32(a10);
            red[ks][1 * 64 + j1] = lo32(a11) + hi32(a11);
            red[ks][2 * 64 + j0] = lo32(a20) + hi32(a20);
            red[ks][2 * 64 + j1] = lo32(a21) + hi32(a21);
            red[ks][3 * 64 + j0] = lo32(a30) + hi32(a30);
            red[ks][3 * 64 + j1] = lo32(a31) + hi32(a31);
        }
        __syncthreads();

        if (is_prod) {
            float s0 = red[0][tid]  + red[1][tid]  + red[2][tid]  + red[3][tid];
            float s1 = red[4][tid]  + red[5][tid]  + red[6][tid]  + red[7][tid];
            float s2 = red[8][tid]  + red[9][tid]  + red[10][tid] + red[11][tid];
            float s3 = red[12][tid] + red[13][tid] + red[14][tid] + red[15][tid];
            float v = tanh_acc(((s0 + s1) + (s2 + s3)) + xwt);

            if (MODE == 0) {
                const size_t gi = own_idx + (size_t)t * H_;
                __nv_bfloat16 hv = __float2bfloat16(v);
                ah[gi] = hv;
                al[gi] = __float2bfloat16(v - __bfloat162float(hv));
            } else if (t == T_ - 1) {
                own[(size_t)t * H_] = v;
            }

            if (t <= T_ - 2)
                hs[t & 1][rank * 256 + tid] = v;
        }
        __syncthreads();

        if (t <= T_ - 2 && is_prod) {
            const int pb = t & 1;
            const uint32_t boff = pb ? HS_BUFB : 0u;
            const uint32_t pmb  = pb ? mb1 : mb0;
            uint4 val = *reinterpret_cast<const uint4*>(
                reinterpret_cast<const char*>(&hs[pb][rank * 256]) + sl_off);
            if (rA != rank) st_async_v4(hsd0 + boff + sl_off, pmb, rA, val);
            if (rB != rank) st_async_v4(hsd0 + boff + sl_off, pmb, rB, val);
        }
    }

    cluster_sync();
}

// ---------------------------------------------------------------------------
// FC: out[b][o] = h1_final[b] . W_fc[o] + b_fc[o]
// ---------------------------------------------------------------------------
__global__ __launch_bounds__(256)
void fc_kernel(const float* __restrict__ hsrc,
               const float* __restrict__ Wfc,
               const float* __restrict__ bfc,
               float* __restrict__ out)
{
    __shared__ float hb[H_];
    const int b = blockIdx.x;
    const int o = threadIdx.x;
    for (int i = o; i < H_; i += 256)
        hb[i] = hsrc[((size_t)b * T_ + (T_ - 1)) * H_ + i];
    __syncthreads();

    const float4* w = reinterpret_cast<const float4*>(Wfc + (size_t)o * H_);
    float acc = 0.0f;
#pragma unroll 8
    for (int i = 0; i < H_ / 4; i++) {
        float4 wv = w[i];
        acc += hb[4 * i + 0] * wv.x + hb[4 * i + 1] * wv.y
             + hb[4 * i + 2] * wv.z + hb[4 * i + 3] * wv.w;
    }
    out[(size_t)b * O_ + o] = acc + bfc[o];
}

// ---------------------------------------------------------------------------
// kernel_launch: 8 graph-capturable kernel launches, stream-ordered.
// ---------------------------------------------------------------------------
extern "C" void kernel_launch(void* const* d_in, const int* in_sizes, int n_in,
                              void* d_out, int out_size)
{
    (void)in_sizes; (void)n_in; (void)out_size;
    const float* x    = (const float*)d_in[0];
    const float* Wih0 = (const float*)d_in[1];
    const float* Whh0 = (const float*)d_in[2];
    const float* bih0 = (const float*)d_in[3];
    const float* bhh0 = (const float*)d_in[4];
    const float* Wih1 = (const float*)d_in[5];
    const float* Whh1 = (const float*)d_in[6];
    const float* bih1 = (const float*)d_in[7];
    const float* bhh1 = (const float*)d_in[8];
    const float* Wfc  = (const float*)d_in[9];
    const float* bfc  = (const float*)d_in[10];

    float *xw = nullptr, *x2 = nullptr;
    __nv_bfloat16 *ah = nullptr, *al = nullptr, *wh = nullptr, *wl = nullptr;
    cudaGetSymbolAddress((void**)&xw, g_xw);
    cudaGetSymbolAddress((void**)&x2, g_x2);
    cudaGetSymbolAddress((void**)&ah, g_ah);
    cudaGetSymbolAddress((void**)&al, g_al);
    cudaGetSymbolAddress((void**)&wh, g_wh);
    cudaGetSymbolAddress((void**)&wl, g_wl);

    dim3 mgrid(MROWS / 128, H_ / 128);   // (512, 4)

    // ---- Layer 0: split-convert x/W, HMMA input projection, scan
    //      (h -> bf16 split written directly by the scan epilogue) ----
    conv_split<<<(H_ * D_) / 1024, 256>>>(Wih0, wh, wl);
    conv_split<<<((size_t)MROWS * D_) / 1024, 256>>>(x, ah, al);
    mma_gemm<D_><<<mgrid, 256>>>(ah, al, wh, wl, bih0, bhh0, xw);
    scan_kernel<0><<<128, 512>>>(xw, Whh0, ah, al);

    // ---- Layer 1: W convert, HMMA (A = scan0's fused ah/al), scan ----
    conv_split<<<(H_ * H_) / 1024, 256>>>(Wih1, wh, wl);
    mma_gemm<H_><<<mgrid, 256>>>(ah, al, wh, wl, bih1, bhh1, x2);
    scan_kernel<1><<<128, 512>>>(x2, Whh1, ah, al);

    // ---- FC on final hidden state of layer 1 ----
    fc_kernel<<<B_, 256>>>(x2, Wfc, bfc, (float*)d_out);
}

// round 16
// speedup vs baseline: 2.8216x; 1.1842x over previous
#include <cuda_runtime.h>
#include <cuda_bf16.h>
#include <cstdint>

// Problem dims
#define B_  64
#define T_  1024
#define D_  256
#define H_  512
#define O_  256
#define MROWS (B_ * T_)   // 65536

// ---------------------------------------------------------------------------
// Scratch (allocation-free per harness rules)
// ---------------------------------------------------------------------------
__device__ float g_xw[(size_t)B_ * T_ * H_];
__device__ float g_x2[(size_t)B_ * T_ * H_];
__device__ __nv_bfloat16 g_ah[(size_t)MROWS * H_];   // A-hi (bf16)
__device__ __nv_bfloat16 g_al[(size_t)MROWS * H_];   // A-lo (bf16 residual)
__device__ __nv_bfloat16 g_wh[(size_t)H_ * H_];      // W-hi
__device__ __nv_bfloat16 g_wl[(size_t)H_ * H_];      // W-lo

// ---------------------------------------------------------------------------
// Helpers
// ---------------------------------------------------------------------------
__device__ __forceinline__ void ffma2(unsigned long long &acc,
                                      unsigned long long a,
                                      unsigned long long b) {
    asm("fma.rn.f32x2 %0, %1, %2, %0;" : "+l"(acc) : "l"(a), "l"(b));
}
__device__ __forceinline__ float lo32(unsigned long long u) {
    return __uint_as_float((unsigned)(u & 0xffffffffull));
}
__device__ __forceinline__ float hi32(unsigned long long u) {
    return __uint_as_float((unsigned)(u >> 32));
}
__device__ __forceinline__ float tanh_acc(float x) {
    float a = fabsf(x);
    float e = __expf(-2.0f * a);
    float r = (1.0f - e) / (1.0f + e);
    return (x < 0.0f) ? -r : r;
}
__device__ __forceinline__ uint32_t smem_u32(const void* p) {
    uint32_t a;
    asm("{ .reg .u64 t; cvta.to.shared.u64 t, %1; cvt.u32.u64 %0, t; }"
        : "=r"(a) : "l"(p));
    return a;
}

// ---- mbarrier / DSMEM primitives (scan) ----
__device__ __forceinline__ void mbar_init(uint32_t addr, uint32_t count) {
    asm volatile("mbarrier.init.shared.b64 [%0], %1;" :: "r"(addr), "r"(count) : "memory");
}
__device__ __forceinline__ void mbar_arrive_expect_tx(uint32_t addr, uint32_t bytes) {
    asm volatile("mbarrier.arrive.expect_tx.shared.b64 _, [%0], %1;"
                 :: "r"(addr), "r"(bytes) : "memory");
}
__device__ __forceinline__ void mbar_wait(uint32_t addr, uint32_t parity) {
    asm volatile(
        "{\n\t"
        ".reg .pred P;\n\t"
        "WL_%=:\n\t"
        "mbarrier.try_wait.parity.acquire.cta.shared::cta.b64 P, [%0], %1, 0x989680;\n\t"
        "@!P bra WL_%=;\n\t"
        "}"
        :: "r"(addr), "r"(parity) : "memory");
}
__device__ __forceinline__ void st_async_v4(uint32_t dst_local, uint32_t mbar_local,
                                            int rank, uint4 v) {
    uint32_t dst, rmb;
    asm volatile("mapa.shared::cluster.u32 %0, %1, %2;" : "=r"(dst) : "r"(dst_local), "r"(rank));
    asm volatile("mapa.shared::cluster.u32 %0, %1, %2;" : "=r"(rmb) : "r"(mbar_local), "r"(rank));
    asm volatile(
        "st.async.shared::cluster.mbarrier::complete_tx::bytes.v4.b32 "
        "[%0], {%1, %2, %3, %4}, [%5];"
        :: "r"(dst), "r"(v.x), "r"(v.y), "r"(v.z), "r"(v.w), "r"(rmb) : "memory");
}
__device__ __forceinline__ void cluster_sync() {
    asm volatile("barrier.cluster.arrive.aligned;" ::: "memory");
    asm volatile("barrier.cluster.wait.aligned;"   ::: "memory");
}

// ---- ldmatrix / mma.sync (sm_80-era PTX; legal on compute_103) ----
__device__ __forceinline__ void ldsm_x4(uint32_t &r0, uint32_t &r1,
                                        uint32_t &r2, uint32_t &r3, uint32_t addr) {
    asm volatile("ldmatrix.sync.aligned.m8n8.x4.shared.b16 {%0,%1,%2,%3}, [%4];"
                 : "=r"(r0), "=r"(r1), "=r"(r2), "=r"(r3) : "r"(addr));
}
__device__ __forceinline__ void ldsm_x2(uint32_t &r0, uint32_t &r1, uint32_t addr) {
    asm volatile("ldmatrix.sync.aligned.m8n8.x2.shared.b16 {%0,%1}, [%2];"
                 : "=r"(r0), "=r"(r1) : "r"(addr));
}
__device__ __forceinline__ void mma16816(float &d0, float &d1, float &d2, float &d3,
                                         uint32_t a0, uint32_t a1, uint32_t a2, uint32_t a3,
                                         uint32_t b0, uint32_t b1) {
    asm volatile(
        "mma.sync.aligned.m16n8k16.row.col.f32.bf16.bf16.f32 "
        "{%0,%1,%2,%3}, {%4,%5,%6,%7}, {%8,%9}, {%0,%1,%2,%3};"
        : "+f"(d0), "+f"(d1), "+f"(d2), "+f"(d3)
        : "r"(a0), "r"(a1), "r"(a2), "r"(a3), "r"(b0), "r"(b1));
}

// ---------------------------------------------------------------------------
// fp32 -> (bf16 hi, bf16 lo) split conversion, 4 elems/thread.
// ---------------------------------------------------------------------------
__global__ __launch_bounds__(256)
void conv_split(const float* __restrict__ src,
                __nv_bfloat16* __restrict__ hi,
                __nv_bfloat16* __restrict__ lo)
{
    size_t i = ((size_t)blockIdx.x * 256 + threadIdx.x) * 4;
    float4 v = *reinterpret_cast<const float4*>(src + i);
    __nv_bfloat16 h0 = __float2bfloat16(v.x), h1 = __float2bfloat16(v.y);
    __nv_bfloat16 h2 = __float2bfloat16(v.z), h3 = __float2bfloat16(v.w);
    __nv_bfloat16 l0 = __float2bfloat16(v.x - __bfloat162float(h0));
    __nv_bfloat16 l1 = __float2bfloat16(v.y - __bfloat162float(h1));
    __nv_bfloat16 l2 = __float2bfloat16(v.z - __bfloat162float(h2));
    __nv_bfloat16 l3 = __float2bfloat16(v.w - __bfloat162float(h3));
    __nv_bfloat162 hp0(h0, h1), hp1(h2, h3), lp0(l0, l1), lp1(l2, l3);
    *reinterpret_cast<uint2*>(hi + i) =
        make_uint2(*reinterpret_cast<uint32_t*>(&hp0), *reinterpret_cast<uint32_t*>(&hp1));
    *reinterpret_cast<uint2*>(lo + i) =
        make_uint2(*reinterpret_cast<uint32_t*>(&lp0), *reinterpret_cast<uint32_t*>(&lp1));
}

// ---------------------------------------------------------------------------
// HMMA GEMM (unchanged from R12): C = A @ W^T + bias1 + bias2, fp32-split.
// ---------------------------------------------------------------------------
template <int K>
__global__ __launch_bounds__(256)
void mma_gemm(const __nv_bfloat16* __restrict__ Ah,
              const __nv_bfloat16* __restrict__ Al,
              const __nv_bfloat16* __restrict__ Wh,
              const __nv_bfloat16* __restrict__ Wl,
              const float* __restrict__ bias1,
              const float* __restrict__ bias2,
              float* __restrict__ C)
{
    __shared__ alignas(1024) unsigned char smA[16384];
    __shared__ alignas(1024) unsigned char smB[16384];

    const int tid  = threadIdx.x;
    const int wid  = tid >> 5;
    const int lane = tid & 31;
    const int m0   = blockIdx.x * 128;
    const int n0   = blockIdx.y * 128;
    const int wm0  = (wid >> 2) * 64;
    const int wn0  = (wid & 3) * 32;

    const uint32_t a_s = smem_u32(smA), b_s = smem_u32(smB);
    const int rowA = lane & 15;
    const int kA8  = (lane & 16) ? 16 : 0;
    const uint32_t xorA = (uint32_t)(rowA & 7) << 4;
    const uint32_t baseA = (uint32_t)(wm0 + rowA) * 128 + kA8;
    const int rowB = lane & 7;
    const int kB8  = (lane & 8) ? 16 : 0;
    const uint32_t xorB = (uint32_t)(rowB & 7) << 4;
    const uint32_t baseB = (uint32_t)(wn0 + rowB) * 128 + kB8;

    float acc[4][4][4];
#pragma unroll
    for (int f = 0; f < 4; f++)
#pragma unroll
        for (int g = 0; g < 4; g++)
#pragma unroll
            for (int e = 0; e < 4; e++) acc[f][g][e] = 0.0f;

    constexpr int CH  = K / 64;
    constexpr int NIT = 3 * CH;

    for (int it = 0; it < NIT; it++) {
        const int p  = it / CH;
        const int kc = it % CH;
        const __nv_bfloat16* As = (p == 1) ? Al : Ah;
        const __nv_bfloat16* Bs = (p == 2) ? Wl : Wh;

        uint4 va[4], vb[4];
#pragma unroll
        for (int i = 0; i < 4; i++) {
            int s   = tid + 256 * i;
            int row = s >> 3, seg = s & 7;
            va[i] = *reinterpret_cast<const uint4*>(
                As + (size_t)(m0 + row) * K + kc * 64 + seg * 8);
            vb[i] = *reinterpret_cast<const uint4*>(
                Bs + (size_t)(n0 + row) * K + kc * 64 + seg * 8);
        }
        __syncthreads();
#pragma unroll
        for (int i = 0; i < 4; i++) {
            int s   = tid + 256 * i;
            int row = s >> 3, seg = s & 7;
            uint32_t off = (uint32_t)(row * 128 + seg * 16);
            off ^= ((off >> 3) & 0x70);
            *reinterpret_cast<uint4*>(smA + off) = va[i];
            *reinterpret_cast<uint4*>(smB + off) = vb[i];
        }
        __syncthreads();

#pragma unroll
        for (int ks = 0; ks < 4; ks++) {
            uint32_t af[4][4], bf[4][2];
#pragma unroll
            for (int f = 0; f < 4; f++) {
                uint32_t addr = a_s + (((baseA + (uint32_t)(f * 2048 + ks * 32)) ^ xorA));
                ldsm_x4(af[f][0], af[f][1], af[f][2], af[f][3], addr);
            }
#pragma unroll
            for (int g = 0; g < 4; g++) {
                uint32_t addr = b_s + (((baseB + (uint32_t)(g * 1024 + ks * 32)) ^ xorB));
                ldsm_x2(bf[g][0], bf[g][1], addr);
            }
#pragma unroll
            for (int f = 0; f < 4; f++)
#pragma unroll
                for (int g = 0; g < 4; g++)
                    mma16816(acc[f][g][0], acc[f][g][1], acc[f][g][2], acc[f][g][3],
                             af[f][0], af[f][1], af[f][2], af[f][3],
                             bf[g][0], bf[g][1]);
        }
    }

    const int r  = lane >> 2;
    const int c4 = lane & 3;
#pragma unroll
    for (int g = 0; g < 4; g++) {
        const int n = n0 + wn0 + g * 8 + c4 * 2;
        float2 bsum;
        bsum.x = bias1[n]     + bias2[n];
        bsum.y = bias1[n + 1] + bias2[n + 1];
#pragma unroll
        for (int f = 0; f < 4; f++) {
            const int mr = m0 + wm0 + f * 16 + r;
            float2 v0, v1;
            v0.x = acc[f][g][0] + bsum.x; v0.y = acc[f][g][1] + bsum.y;
            v1.x = acc[f][g][2] + bsum.x; v1.y = acc[f][g][3] + bsum.y;
            *reinterpret_cast<float2*>(C + (size_t)mr * H_ + n)       = v0;
            *reinterpret_cast<float2*>(C + (size_t)(mr + 8) * H_ + n) = v1;
        }
    }
}

// ---------------------------------------------------------------------------
// Recurrent scan — R12 structure with ONE change: the per-buffer mbarrier is
// split into per-SOURCE-RANK mbarriers (mbar[2][8], own column unused).
//
// Rationale: consumer warp ks reads exactly one source rank's 1KB slice
// (src = ks>>1); warps whose source is the LOCAL rank need no wait at all
// (staging store is ordered by the previous step's __syncthreads). Each
// warp now gates only on its own peer's 64x16B tx (expect 1024 B), so
// early-arriving slices start FFMA2 work while later slices are still in
// flight — fabric drain overlaps with compute.
//
// Re-arms are distributed: lane 0 of even warp ks=2r re-arms mb[b][r] after
// passing its own wait (parity persists, so the odd sibling warp's pending
// try_wait is unaffected — same argument as R12's tid0 re-arm).
// Everything else (thread map, staging, both per-step barriers, 7-peer
// st.async publish, W-in-registers) is byte-for-byte R12.
// ---------------------------------------------------------------------------
template <bool WRITE_ALL>
__global__ __launch_bounds__(512, 1) __cluster_dims__(8, 1, 1)
void scan_kernel(float* __restrict__ xw, const float* __restrict__ Whh)
{
    __shared__ alignas(16) float hs[2][8 * 256];
    __shared__ alignas(16) float red[16][260];
    __shared__ alignas(8) unsigned long long mbar[2][8];   // [buf][src_rank]

    const int tid  = threadIdx.x;
    const int lane = tid & 31;
    const int rank = blockIdx.x & 7;
    const int cb   = (blockIdx.x >> 3) * 4;
    const int jp   = tid & 31;
    const int ks   = tid >> 5;
    const int jg0  = rank * 64 + jp * 2;
    const int k0   = ks * 32;

    ulonglong2 Wa[8], Wb[8];
    {
        const ulonglong2* w0 =
            reinterpret_cast<const ulonglong2*>(Whh + (size_t)jg0 * H_ + k0);
        const ulonglong2* w1 =
            reinterpret_cast<const ulonglong2*>(Whh + (size_t)(jg0 + 1) * H_ + k0);
#pragma unroll
        for (int i = 0; i < 8; i++) { Wa[i] = w0[i]; Wb[i] = w1[i]; }
    }

    const int oc = (tid >> 6) & 3;
    const int oj = tid & 63;
    const bool is_prod = (tid < 256);
    float* own = xw + (size_t)(cb + oc) * T_ * H_ + rank * 64 + oj;

    const uint32_t mbbase = smem_u32(&mbar[0][0]);
    const uint32_t hsd0   = smem_u32(&hs[0][rank * 256]);
    constexpr uint32_t HS_BUFB = 8 * 256 * 4;

    const int rA = (tid >> 6) & 3;
    const int rB = rA + 4;
    const uint32_t sl_off = (uint32_t)(tid & 63) * 16u;

    // Consumer role: which source rank this warp's k-range lives in.
    const int  src_r     = ks >> 1;
    const bool need_wait = (src_r != rank);
    const uint32_t mb_src0 = mbbase + (uint32_t)src_r * 8u;          // buf 0
    // Publisher: tx from THIS CTA count on mbar[buf][rank] at the DEST.
    const uint32_t mb_pub0 = mbbase + (uint32_t)rank * 8u;           // buf 0
    // Re-arm role: lane 0 of even warps re-arms its source's mbarrier.
    const bool rearm = (lane == 0) && ((ks & 1) == 0) && need_wait;

    if (tid == 0) {
#pragma unroll
        for (int b = 0; b < 2; b++)
            for (int r = 0; r < 8; r++)
                if (r != rank) {
                    uint32_t a = mbbase + (uint32_t)(b * 8 + r) * 8u;
                    mbar_init(a, 1);
                    mbar_arrive_expect_tx(a, 1024);   // arm steps 0 and 1
                }
    }
    __syncthreads();
    cluster_sync();                          // mbarriers live before any tx

    const int hoff = (ks >> 1) * 256 + (ks & 1) * 32;

    // ---- t = 0: h0 = tanh(xw[0]); local slice + publish into buf 0 ----
    {
        if (is_prod) {
            float v = tanh_acc(own[0]);
            if (WRITE_ALL) own[0] = v;
            hs[0][rank * 256 + tid] = v;
        }
        __syncthreads();
        if (is_prod) {
            uint4 val = *reinterpret_cast<const uint4*>(
                reinterpret_cast<const char*>(&hs[0][rank * 256]) + sl_off);
            if (rA != rank) st_async_v4(hsd0 + sl_off, mb_pub0, rA, val);
            if (rB != rank) st_async_v4(hsd0 + sl_off, mb_pub0, rB, val);
        }
    }

    for (int t = 1; t < T_; t++) {
        float xwt = is_prod ? own[(size_t)t * H_] : 0.0f;

        const int s = t - 1;
        const int b = s & 1;
        // Wait ONLY for this warp's source slice (none if local).
        if (need_wait)
            mbar_wait(mb_src0 + (uint32_t)b * 64u, (uint32_t)((s >> 1) & 1));
        // Distributed re-arm for step t+1 (this mbarrier's next phase).
        if (rearm && t <= T_ - 3)
            mbar_arrive_expect_tx(mb_src0 + (uint32_t)b * 64u, 1024);

        const float* hb = hs[b] + hoff;
        const ulonglong2* p0 = reinterpret_cast<const ulonglong2*>(hb + 0 * 64);
        const ulonglong2* p1 = reinterpret_cast<const ulonglong2*>(hb + 1 * 64);
        const ulonglong2* p2 = reinterpret_cast<const ulonglong2*>(hb + 2 * 64);
        const ulonglong2* p3 = reinterpret_cast<const ulonglong2*>(hb + 3 * 64);

        unsigned long long a00 = 0ull, a01 = 0ull;
        unsigned long long a10 = 0ull, a11 = 0ull;
        unsigned long long a20 = 0ull, a21 = 0ull;
        unsigned long long a30 = 0ull, a31 = 0ull;
#pragma unroll
        for (int i = 0; i < 8; i++) {
            ulonglong2 w0 = Wa[i], w1 = Wb[i];
            ulonglong2 v0 = p0[i];
            ffma2(a00, v0.x, w0.x); ffma2(a00, v0.y, w0.y);
            ffma2(a01, v0.x, w1.x); ffma2(a01, v0.y, w1.y);
            ulonglong2 v1 = p1[i];
            ffma2(a10, v1.x, w0.x); ffma2(a10, v1.y, w0.y);
            ffma2(a11, v1.x, w1.x); ffma2(a11, v1.y, w1.y);
            ulonglong2 v2 = p2[i];
            ffma2(a20, v2.x, w0.x); ffma2(a20, v2.y, w0.y);
            ffma2(a21, v2.x, w1.x); ffma2(a21, v2.y, w1.y);
            ulonglong2 v3 = p3[i];
            ffma2(a30, v3.x, w0.x); ffma2(a30, v3.y, w0.y);
            ffma2(a31, v3.x, w1.x); ffma2(a31, v3.y, w1.y);
        }
        {
            const int j0 = jp * 2, j1 = jp * 2 + 1;
            red[ks][0 * 64 + j0] = lo32(a00) + hi32(a00);
            red[ks][0 * 64 + j1] = lo32(a01) + hi32(a01);
            red[ks][1 * 64 + j0] = lo32(a10) + hi32(a10);
            red[ks][1 * 64 + j1] = lo32(a11) + hi32(a11);
            red[ks][2 * 64 + j0] = lo32(a20) + hi32(a20);
            red[ks][2 * 64 + j1] = lo32(a21) + hi32(a21);
            red[ks][3 * 64 + j0] = lo32(a30) + hi32(a30);
            red[ks][3 * 64 + j1] = lo32(a31) + hi32(a31);
        }
        __syncthreads();

        if (is_prod) {
            float s0 = red[0][tid]  + red[1][tid]  + red[2][tid]  + red[3][tid];
            float s1 = red[4][tid]  + red[5][tid]  + red[6][tid]  + red[7][tid];
            float s2 = red[8][tid]  + red[9][tid]  + red[10][tid] + red[11][tid];
            float s3 = red[12][tid] + red[13][tid] + red[14][tid] + red[15][tid];
            float v = tanh_acc(((s0 + s1) + (s2 + s3)) + xwt);

            if (WRITE_ALL || t == T_ - 1)
                own[(size_t)t * H_] = v;

            if (t <= T_ - 2)
                hs[t & 1][rank * 256 + tid] = v;
        }
        __syncthreads();

        if (t <= T_ - 2 && is_prod) {
            const int pb = t & 1;
            const uint32_t boff = pb ? HS_BUFB : 0u;
            const uint32_t pmb  = mb_pub0 + (uint32_t)pb * 64u;
            uint4 val = *reinterpret_cast<const uint4*>(
                reinterpret_cast<const char*>(&hs[pb][rank * 256]) + sl_off);
            if (rA != rank) st_async_v4(hsd0 + boff + sl_off, pmb, rA, val);
            if (rB != rank) st_async_v4(hsd0 + boff + sl_off, pmb, rB, val);
        }
    }

    cluster_sync();
}

// ---------------------------------------------------------------------------
// FC: out[b][o] = h1_final[b] . W_fc[o] + b_fc[o]
// ---------------------------------------------------------------------------
__global__ __launch_bounds__(256)
void fc_kernel(const float* __restrict__ hsrc,
               const float* __restrict__ Wfc,
               const float* __restrict__ bfc,
               float* __restrict__ out)
{
    __shared__ float hb[H_];
    const int b = blockIdx.x;
    const int o = threadIdx.x;
    for (int i = o; i < H_; i += 256)
        hb[i] = hsrc[((size_t)b * T_ + (T_ - 1)) * H_ + i];
    __syncthreads();

    const float4* w = reinterpret_cast<const float4*>(Wfc + (size_t)o * H_);
    float acc = 0.0f;
#pragma unroll 8
    for (int i = 0; i < H_ / 4; i++) {
        float4 wv = w[i];
        acc += hb[4 * i + 0] * wv.x + hb[4 * i + 1] * wv.y
             + hb[4 * i + 2] * wv.z + hb[4 * i + 3] * wv.w;
    }
    out[(size_t)b * O_ + o] = acc + bfc[o];
}

// ---------------------------------------------------------------------------
// kernel_launch: 9 graph-capturable kernel launches, stream-ordered.
// ---------------------------------------------------------------------------
extern "C" void kernel_launch(void* const* d_in, const int* in_sizes, int n_in,
                              void* d_out, int out_size)
{
    (void)in_sizes; (void)n_in; (void)out_size;
    const float* x    = (const float*)d_in[0];
    const float* Wih0 = (const float*)d_in[1];
    const float* Whh0 = (const float*)d_in[2];
    const float* bih0 = (const float*)d_in[3];
    const float* bhh0 = (const float*)d_in[4];
    const float* Wih1 = (const float*)d_in[5];
    const float* Whh1 = (const float*)d_in[6];
    const float* bih1 = (const float*)d_in[7];
    const float* bhh1 = (const float*)d_in[8];
    const float* Wfc  = (const float*)d_in[9];
    const float* bfc  = (const float*)d_in[10];

    float *xw = nullptr, *x2 = nullptr;
    __nv_bfloat16 *ah = nullptr, *al = nullptr, *wh = nullptr, *wl = nullptr;
    cudaGetSymbolAddress((void**)&xw, g_xw);
    cudaGetSymbolAddress((void**)&x2, g_x2);
    cudaGetSymbolAddress((void**)&ah, g_ah);
    cudaGetSymbolAddress((void**)&al, g_al);
    cudaGetSymbolAddress((void**)&wh, g_wh);
    cudaGetSymbolAddress((void**)&wl, g_wl);

    dim3 mgrid(MROWS / 128, H_ / 128);   // (512, 4)

    // ---- Layer 0: split-convert, HMMA input projection, scan ----
    conv_split<<<(H_ * D_) / 1024, 256>>>(Wih0, wh, wl);
    conv_split<<<((size_t)MROWS * D_) / 1024, 256>>>(x, ah, al);
    mma_gemm<D_><<<mgrid, 256>>>(ah, al, wh, wl, bih0, bhh0, xw);
    scan_kernel<true><<<128, 512>>>(xw, Whh0);

    // ---- Layer 1 ----
    conv_split<<<(H_ * H_) / 1024, 256>>>(Wih1, wh, wl);
    conv_split<<<((size_t)MROWS * H_) / 1024, 256>>>(xw, ah, al);
    mma_gemm<H_><<<mgrid, 256>>>(ah, al, wh, wl, bih1, bhh1, x2);
    scan_kernel<false><<<128, 512>>>(x2, Whh1);

    // ---- FC on final hidden state of layer 1 ----
    fc_kernel<<<B_, 256>>>(x2, Wfc, bfc, (float*)d_out);
}

// round 17
// speedup vs baseline: 2.8995x; 1.0276x over previous
#include <cuda_runtime.h>
#include <cuda_bf16.h>
#include <cstdint>

// Problem dims
#define B_  64
#define T_  1024
#define D_  256
#define H_  512
#define O_  256
#define MROWS (B_ * T_)   // 65536

// ---------------------------------------------------------------------------
// Scratch (allocation-free per harness rules)
// ---------------------------------------------------------------------------
__device__ float g_xw[(size_t)B_ * T_ * H_];
__device__ float g_x2[(size_t)B_ * T_ * H_];
__device__ __nv_bfloat16 g_ah[(size_t)MROWS * H_];   // A-hi (bf16)
__device__ __nv_bfloat16 g_al[(size_t)MROWS * H_];   // A-lo (bf16 residual)
__device__ __nv_bfloat16 g_wh[(size_t)H_ * H_];      // W-hi
__device__ __nv_bfloat16 g_wl[(size_t)H_ * H_];      // W-lo

// ---------------------------------------------------------------------------
// Helpers
// ---------------------------------------------------------------------------
__device__ __forceinline__ void ffma2(unsigned long long &acc,
                                      unsigned long long a,
                                      unsigned long long b) {
    asm("fma.rn.f32x2 %0, %1, %2, %0;" : "+l"(acc) : "l"(a), "l"(b));
}
__device__ __forceinline__ float lo32(unsigned long long u) {
    return __uint_as_float((unsigned)(u & 0xffffffffull));
}
__device__ __forceinline__ float hi32(unsigned long long u) {
    return __uint_as_float((unsigned)(u >> 32));
}
__device__ __forceinline__ float tanh_acc(float x) {
    float a = fabsf(x);
    float e = __expf(-2.0f * a);
    float r = (1.0f - e) / (1.0f + e);
    return (x < 0.0f) ? -r : r;
}
__device__ __forceinline__ uint32_t smem_u32(const void* p) {
    uint32_t a;
    asm("{ .reg .u64 t; cvta.to.shared.u64 t, %1; cvt.u32.u64 %0, t; }"
        : "=r"(a) : "l"(p));
    return a;
}

// ---- mbarrier / DSMEM primitives (scan) ----
__device__ __forceinline__ void mbar_init(uint32_t addr, uint32_t count) {
    asm volatile("mbarrier.init.shared.b64 [%0], %1;" :: "r"(addr), "r"(count) : "memory");
}
__device__ __forceinline__ void mbar_arrive_expect_tx(uint32_t addr, uint32_t bytes) {
    asm volatile("mbarrier.arrive.expect_tx.shared.b64 _, [%0], %1;"
                 :: "r"(addr), "r"(bytes) : "memory");
}
__device__ __forceinline__ void mbar_wait(uint32_t addr, uint32_t parity) {
    asm volatile(
        "{\n\t"
        ".reg .pred P;\n\t"
        "WL_%=:\n\t"
        "mbarrier.try_wait.parity.acquire.cta.shared::cta.b64 P, [%0], %1, 0x989680;\n\t"
        "@!P bra WL_%=;\n\t"
        "}"
        :: "r"(addr), "r"(parity) : "memory");
}
__device__ __forceinline__ void st_async_v4(uint32_t dst_local, uint32_t mbar_local,
                                            int rank, uint4 v) {
    uint32_t dst, rmb;
    asm volatile("mapa.shared::cluster.u32 %0, %1, %2;" : "=r"(dst) : "r"(dst_local), "r"(rank));
    asm volatile("mapa.shared::cluster.u32 %0, %1, %2;" : "=r"(rmb) : "r"(mbar_local), "r"(rank));
    asm volatile(
        "st.async.shared::cluster.mbarrier::complete_tx::bytes.v4.b32 "
        "[%0], {%1, %2, %3, %4}, [%5];"
        :: "r"(dst), "r"(v.x), "r"(v.y), "r"(v.z), "r"(v.w), "r"(rmb) : "memory");
}
__device__ __forceinline__ void cluster_sync() {
    asm volatile("barrier.cluster.arrive.aligned;" ::: "memory");
    asm volatile("barrier.cluster.wait.aligned;"   ::: "memory");
}

// ---- ldmatrix / mma.sync (sm_80-era PTX; legal on compute_103) ----
__device__ __forceinline__ void ldsm_x4(uint32_t &r0, uint32_t &r1,
                                        uint32_t &r2, uint32_t &r3, uint32_t addr) {
    asm volatile("ldmatrix.sync.aligned.m8n8.x4.shared.b16 {%0,%1,%2,%3}, [%4];"
                 : "=r"(r0), "=r"(r1), "=r"(r2), "=r"(r3) : "r"(addr));
}
__device__ __forceinline__ void ldsm_x2(uint32_t &r0, uint32_t &r1, uint32_t addr) {
    asm volatile("ldmatrix.sync.aligned.m8n8.x2.shared.b16 {%0,%1}, [%2];"
                 : "=r"(r0), "=r"(r1) : "r"(addr));
}
__device__ __forceinline__ void mma16816(float &d0, float &d1, float &d2, float &d3,
                                         uint32_t a0, uint32_t a1, uint32_t a2, uint32_t a3,
                                         uint32_t b0, uint32_t b1) {
    asm volatile(
        "mma.sync.aligned.m16n8k16.row.col.f32.bf16.bf16.f32 "
        "{%0,%1,%2,%3}, {%4,%5,%6,%7}, {%8,%9}, {%0,%1,%2,%3};"
        : "+f"(d0), "+f"(d1), "+f"(d2), "+f"(d3)
        : "r"(a0), "r"(a1), "r"(a2), "r"(a3), "r"(b0), "r"(b1));
}

// ---------------------------------------------------------------------------
// fp32 -> (bf16 hi, bf16 lo) split conversion, 4 elems/thread.
// ---------------------------------------------------------------------------
__global__ __launch_bounds__(256)
void conv_split(const float* __restrict__ src,
                __nv_bfloat16* __restrict__ hi,
                __nv_bfloat16* __restrict__ lo)
{
    size_t i = ((size_t)blockIdx.x * 256 + threadIdx.x) * 4;
    float4 v = *reinterpret_cast<const float4*>(src + i);
    __nv_bfloat16 h0 = __float2bfloat16(v.x), h1 = __float2bfloat16(v.y);
    __nv_bfloat16 h2 = __float2bfloat16(v.z), h3 = __float2bfloat16(v.w);
    __nv_bfloat16 l0 = __float2bfloat16(v.x - __bfloat162float(h0));
    __nv_bfloat16 l1 = __float2bfloat16(v.y - __bfloat162float(h1));
    __nv_bfloat16 l2 = __float2bfloat16(v.z - __bfloat162float(h2));
    __nv_bfloat16 l3 = __float2bfloat16(v.w - __bfloat162float(h3));
    __nv_bfloat162 hp0(h0, h1), hp1(h2, h3), lp0(l0, l1), lp1(l2, l3);
    *reinterpret_cast<uint2*>(hi + i) =
        make_uint2(*reinterpret_cast<uint32_t*>(&hp0), *reinterpret_cast<uint32_t*>(&hp1));
    *reinterpret_cast<uint2*>(lo + i) =
        make_uint2(*reinterpret_cast<uint32_t*>(&lp0), *reinterpret_cast<uint32_t*>(&lp1));
}

// ---------------------------------------------------------------------------
// HMMA GEMM, R17: cp.async double-buffered pipeline.
// C = A @ W^T + bias1 + bias2, fp32-split (3 passes Ah*Wh + Al*Wh + Ah*Wl).
// CTA tile 128x128, 8 warps (2M x 4N), warp tile 64x32 via m16n8k16.
// Dynamic smem 64KB: A buffers at [0,16K),[16K,32K); B at [32K,48K),[48K,64K).
// 2-stage pipeline: chunk it+1 prefetched via cp.async.cg (8x16B/thread)
// while chunk it computes; wait_group 1 keeps one chunk in flight.
// ---------------------------------------------------------------------------
template <int K>
__global__ __launch_bounds__(256, 2)
void mma_gemm(const __nv_bfloat16* __restrict__ Ah,
              const __nv_bfloat16* __restrict__ Al,
              const __nv_bfloat16* __restrict__ Wh,
              const __nv_bfloat16* __restrict__ Wl,
              const float* __restrict__ bias1,
              const float* __restrict__ bias2,
              float* __restrict__ C)
{
    extern __shared__ unsigned char dynsm[];
    const uint32_t smbase = smem_u32(dynsm);

    const int tid  = threadIdx.x;
    const int wid  = tid >> 5;
    const int lane = tid & 31;
    const int m0   = blockIdx.x * 128;
    const int n0   = blockIdx.y * 128;
    const int wm0  = (wid >> 2) * 64;
    const int wn0  = (wid & 3) * 32;

    const int rowA = lane & 15;
    const int kA8  = (lane & 16) ? 16 : 0;
    const uint32_t xorA = (uint32_t)(rowA & 7) << 4;
    const uint32_t baseA = (uint32_t)(wm0 + rowA) * 128 + kA8;
    const int rowB = lane & 7;
    const int kB8  = (lane & 8) ? 16 : 0;
    const uint32_t xorB = (uint32_t)(rowB & 7) << 4;
    const uint32_t baseB = (uint32_t)(wn0 + rowB) * 128 + kB8;

    // Per-thread swizzled smem offsets for the 4 load segments (static).
    uint32_t soff[4];
#pragma unroll
    for (int i = 0; i < 4; i++) {
        int s   = tid + 256 * i;
        int row = s >> 3, seg = s & 7;
        uint32_t off = (uint32_t)(row * 128 + seg * 16);
        soff[i] = off ^ ((off >> 3) & 0x70);
    }

    float acc[4][4][4];
#pragma unroll
    for (int f = 0; f < 4; f++)
#pragma unroll
        for (int g = 0; g < 4; g++)
#pragma unroll
            for (int e = 0; e < 4; e++) acc[f][g][e] = 0.0f;

    constexpr int CH  = K / 64;
    constexpr int NIT = 3 * CH;

    // Issue one chunk's loads into buffer `buf` and commit the group.
    auto issue_chunk = [&](int it, int buf) {
        const int p  = it / CH;
        const int kc = it % CH;
        const __nv_bfloat16* As = (p == 1) ? Al : Ah;
        const __nv_bfloat16* Bs = (p == 2) ? Wl : Wh;
        const uint32_t abase = smbase + (uint32_t)buf * 16384u;
        const uint32_t bbase = smbase + 32768u + (uint32_t)buf * 16384u;
#pragma unroll
        for (int i = 0; i < 4; i++) {
            int s   = tid + 256 * i;
            int row = s >> 3, seg = s & 7;
            const void* ga = As + (size_t)(m0 + row) * K + kc * 64 + seg * 8;
            const void* gb = Bs + (size_t)(n0 + row) * K + kc * 64 + seg * 8;
            asm volatile("cp.async.cg.shared.global [%0], [%1], 16;"
                         :: "r"(abase + soff[i]), "l"(ga));
            asm volatile("cp.async.cg.shared.global [%0], [%1], 16;"
                         :: "r"(bbase + soff[i]), "l"(gb));
        }
        asm volatile("cp.async.commit_group;" ::: "memory");
    };

    issue_chunk(0, 0);

    for (int it = 0; it < NIT; it++) {
        if (it + 1 < NIT) {
            issue_chunk(it + 1, (it + 1) & 1);
            asm volatile("cp.async.wait_group 1;" ::: "memory");
        } else {
            asm volatile("cp.async.wait_group 0;" ::: "memory");
        }
        __syncthreads();   // all threads' chunk-it data landed

        const uint32_t a_s = smbase + (uint32_t)(it & 1) * 16384u;
        const uint32_t b_s = smbase + 32768u + (uint32_t)(it & 1) * 16384u;

#pragma unroll
        for (int ks = 0; ks < 4; ks++) {
            uint32_t af[4][4], bf[4][2];
#pragma unroll
            for (int f = 0; f < 4; f++) {
                uint32_t addr = a_s + (((baseA + (uint32_t)(f * 2048 + ks * 32)) ^ xorA));
                ldsm_x4(af[f][0], af[f][1], af[f][2], af[f][3], addr);
            }
#pragma unroll
            for (int g = 0; g < 4; g++) {
                uint32_t addr = b_s + (((baseB + (uint32_t)(g * 1024 + ks * 32)) ^ xorB));
                ldsm_x2(bf[g][0], bf[g][1], addr);
            }
#pragma unroll
            for (int f = 0; f < 4; f++)
#pragma unroll
                for (int g = 0; g < 4; g++)
                    mma16816(acc[f][g][0], acc[f][g][1], acc[f][g][2], acc[f][g][3],
                             af[f][0], af[f][1], af[f][2], af[f][3],
                             bf[g][0], bf[g][1]);
        }
        __syncthreads();   // compute done before this buffer is re-filled (it+2)
    }

    const int r  = lane >> 2;
    const int c4 = lane & 3;
#pragma unroll
    for (int g = 0; g < 4; g++) {
        const int n = n0 + wn0 + g * 8 + c4 * 2;
        float2 bsum;
        bsum.x = bias1[n]     + bias2[n];
        bsum.y = bias1[n + 1] + bias2[n + 1];
#pragma unroll
        for (int f = 0; f < 4; f++) {
            const int mr = m0 + wm0 + f * 16 + r;
            float2 v0, v1;
            v0.x = acc[f][g][0] + bsum.x; v0.y = acc[f][g][1] + bsum.y;
            v1.x = acc[f][g][2] + bsum.x; v1.y = acc[f][g][3] + bsum.y;
            *reinterpret_cast<float2*>(C + (size_t)mr * H_ + n)       = v0;
            *reinterpret_cast<float2*>(C + (size_t)(mr + 8) * H_ + n) = v1;
        }
    }
}

// ---------------------------------------------------------------------------
// Recurrent scan — unchanged from R16 (per-source-rank mbarriers).
// ---------------------------------------------------------------------------
template <bool WRITE_ALL>
__global__ __launch_bounds__(512, 1) __cluster_dims__(8, 1, 1)
void scan_kernel(float* __restrict__ xw, const float* __restrict__ Whh)
{
    __shared__ alignas(16) float hs[2][8 * 256];
    __shared__ alignas(16) float red[16][260];
    __shared__ alignas(8) unsigned long long mbar[2][8];   // [buf][src_rank]

    const int tid  = threadIdx.x;
    const int lane = tid & 31;
    const int rank = blockIdx.x & 7;
    const int cb   = (blockIdx.x >> 3) * 4;
    const int jp   = tid & 31;
    const int ks   = tid >> 5;
    const int jg0  = rank * 64 + jp * 2;
    const int k0   = ks * 32;

    ulonglong2 Wa[8], Wb[8];
    {
        const ulonglong2* w0 =
            reinterpret_cast<const ulonglong2*>(Whh + (size_t)jg0 * H_ + k0);
        const ulonglong2* w1 =
            reinterpret_cast<const ulonglong2*>(Whh + (size_t)(jg0 + 1) * H_ + k0);
#pragma unroll
        for (int i = 0; i < 8; i++) { Wa[i] = w0[i]; Wb[i] = w1[i]; }
    }

    const int oc = (tid >> 6) & 3;
    const int oj = tid & 63;
    const bool is_prod = (tid < 256);
    float* own = xw + (size_t)(cb + oc) * T_ * H_ + rank * 64 + oj;

    const uint32_t mbbase = smem_u32(&mbar[0][0]);
    const uint32_t hsd0   = smem_u32(&hs[0][rank * 256]);
    constexpr uint32_t HS_BUFB = 8 * 256 * 4;

    const int rA = (tid >> 6) & 3;
    const int rB = rA + 4;
    const uint32_t sl_off = (uint32_t)(tid & 63) * 16u;

    const int  src_r     = ks >> 1;
    const bool need_wait = (src_r != rank);
    const uint32_t mb_src0 = mbbase + (uint32_t)src_r * 8u;
    const uint32_t mb_pub0 = mbbase + (uint32_t)rank * 8u;
    const bool rearm = (lane == 0) && ((ks & 1) == 0) && need_wait;

    if (tid == 0) {
#pragma unroll
        for (int b = 0; b < 2; b++)
            for (int r = 0; r < 8; r++)
                if (r != rank) {
                    uint32_t a = mbbase + (uint32_t)(b * 8 + r) * 8u;
                    mbar_init(a, 1);
                    mbar_arrive_expect_tx(a, 1024);
                }
    }
    __syncthreads();
    cluster_sync();

    const int hoff = (ks >> 1) * 256 + (ks & 1) * 32;

    {
        if (is_prod) {
            float v = tanh_acc(own[0]);
            if (WRITE_ALL) own[0] = v;
            hs[0][rank * 256 + tid] = v;
        }
        __syncthreads();
        if (is_prod) {
            uint4 val = *reinterpret_cast<const uint4*>(
                reinterpret_cast<const char*>(&hs[0][rank * 256]) + sl_off);
            if (rA != rank) st_async_v4(hsd0 + sl_off, mb_pub0, rA, val);
            if (rB != rank) st_async_v4(hsd0 + sl_off, mb_pub0, rB, val);
        }
    }

    for (int t = 1; t < T_; t++) {
        float xwt = is_prod ? own[(size_t)t * H_] : 0.0f;

        const int s = t - 1;
        const int b = s & 1;
        if (need_wait)
            mbar_wait(mb_src0 + (uint32_t)b * 64u, (uint32_t)((s >> 1) & 1));
        if (rearm && t <= T_ - 3)
            mbar_arrive_expect_tx(mb_src0 + (uint32_t)b * 64u, 1024);

        const float* hb = hs[b] + hoff;
        const ulonglong2* p0 = reinterpret_cast<const ulonglong2*>(hb + 0 * 64);
        const ulonglong2* p1 = reinterpret_cast<const ulonglong2*>(hb + 1 * 64);
        const ulonglong2* p2 = reinterpret_cast<const ulonglong2*>(hb + 2 * 64);
        const ulonglong2* p3 = reinterpret_cast<const ulonglong2*>(hb + 3 * 64);

        unsigned long long a00 = 0ull, a01 = 0ull;
        unsigned long long a10 = 0ull, a11 = 0ull;
        unsigned long long a20 = 0ull, a21 = 0ull;
        unsigned long long a30 = 0ull, a31 = 0ull;
#pragma unroll
        for (int i = 0; i < 8; i++) {
            ulonglong2 w0 = Wa[i], w1 = Wb[i];
            ulonglong2 v0 = p0[i];
            ffma2(a00, v0.x, w0.x); ffma2(a00, v0.y, w0.y);
            ffma2(a01, v0.x, w1.x); ffma2(a01, v0.y, w1.y);
            ulonglong2 v1 = p1[i];
            ffma2(a10, v1.x, w0.x); ffma2(a10, v1.y, w0.y);
            ffma2(a11, v1.x, w1.x); ffma2(a11, v1.y, w1.y);
            ulonglong2 v2 = p2[i];
            ffma2(a20, v2.x, w0.x); ffma2(a20, v2.y, w0.y);
            ffma2(a21, v2.x, w1.x); ffma2(a21, v2.y, w1.y);
            ulonglong2 v3 = p3[i];
            ffma2(a30, v3.x, w0.x); ffma2(a30, v3.y, w0.y);
            ffma2(a31, v3.x, w1.x); ffma2(a31, v3.y, w1.y);
        }
        {
            const int j0 = jp * 2, j1 = jp * 2 + 1;
            red[ks][0 * 64 + j0] = lo32(a00) + hi32(a00);
            red[ks][0 * 64 + j1] = lo32(a01) + hi32(a01);
            red[ks][1 * 64 + j0] = lo32(a10) + hi32(a10);
            red[ks][1 * 64 + j1] = lo32(a11) + hi32(a11);
            red[ks][2 * 64 + j0] = lo32(a20) + hi32(a20);
            red[ks][2 * 64 + j1] = lo32(a21) + hi32(a21);
            red[ks][3 * 64 + j0] = lo32(a30) + hi32(a30);
            red[ks][3 * 64 + j1] = lo32(a31) + hi32(a31);
        }
        __syncthreads();

        if (is_prod) {
            float s0 = red[0][tid]  + red[1][tid]  + red[2][tid]  + red[3][tid];
            float s1 = red[4][tid]  + red[5][tid]  + red[6][tid]  + red[7][tid];
            float s2 = red[8][tid]  + red[9][tid]  + red[10][tid] + red[11][tid];
            float s3 = red[12][tid] + red[13][tid] + red[14][tid] + red[15][tid];
            float v = tanh_acc(((s0 + s1) + (s2 + s3)) + xwt);

            if (WRITE_ALL || t == T_ - 1)
                own[(size_t)t * H_] = v;

            if (t <= T_ - 2)
                hs[t & 1][rank * 256 + tid] = v;
        }
        __syncthreads();

        if (t <= T_ - 2 && is_prod) {
            const int pb = t & 1;
            const uint32_t boff = pb ? HS_BUFB : 0u;
            const uint32_t pmb  = mb_pub0 + (uint32_t)pb * 64u;
            uint4 val = *reinterpret_cast<const uint4*>(
                reinterpret_cast<const char*>(&hs[pb][rank * 256]) + sl_off);
            if (rA != rank) st_async_v4(hsd0 + boff + sl_off, pmb, rA, val);
            if (rB != rank) st_async_v4(hsd0 + boff + sl_off, pmb, rB, val);
        }
    }

    cluster_sync();
}

// ---------------------------------------------------------------------------
// FC: out[b][o] = h1_final[b] . W_fc[o] + b_fc[o]
// ---------------------------------------------------------------------------
__global__ __launch_bounds__(256)
void fc_kernel(const float* __restrict__ hsrc,
               const float* __restrict__ Wfc,
               const float* __restrict__ bfc,
               float* __restrict__ out)
{
    __shared__ float hb[H_];
    const int b = blockIdx.x;
    const int o = threadIdx.x;
    for (int i = o; i < H_; i += 256)
        hb[i] = hsrc[((size_t)b * T_ + (T_ - 1)) * H_ + i];
    __syncthreads();

    const float4* w = reinterpret_cast<const float4*>(Wfc + (size_t)o * H_);
    float acc = 0.0f;
#pragma unroll 8
    for (int i = 0; i < H_ / 4; i++) {
        float4 wv = w[i];
        acc += hb[4 * i + 0] * wv.x + hb[4 * i + 1] * wv.y
             + hb[4 * i + 2] * wv.z + hb[4 * i + 3] * wv.w;
    }
    out[(size_t)b * O_ + o] = acc + bfc[o];
}

// ---------------------------------------------------------------------------
// kernel_launch: 9 graph-capturable kernel launches, stream-ordered.
// cudaFuncSetAttribute is host-side/non-stream (capture-legal, idempotent).
// ---------------------------------------------------------------------------
extern "C" void kernel_launch(void* const* d_in, const int* in_sizes, int n_in,
                              void* d_out, int out_size)
{
    (void)in_sizes; (void)n_in; (void)out_size;
    const float* x    = (const float*)d_in[0];
    const float* Wih0 = (const float*)d_in[1];
    const float* Whh0 = (const float*)d_in[2];
    const float* bih0 = (const float*)d_in[3];
    const float* bhh0 = (const float*)d_in[4];
    const float* Wih1 = (const float*)d_in[5];
    const float* Whh1 = (const float*)d_in[6];
    const float* bih1 = (const float*)d_in[7];
    const float* bhh1 = (const float*)d_in[8];
    const float* Wfc  = (const float*)d_in[9];
    const float* bfc  = (const float*)d_in[10];

    float *xw = nullptr, *x2 = nullptr;
    __nv_bfloat16 *ah = nullptr, *al = nullptr, *wh = nullptr, *wl = nullptr;
    cudaGetSymbolAddress((void**)&xw, g_xw);
    cudaGetSymbolAddress((void**)&x2, g_x2);
    cudaGetSymbolAddress((void**)&ah, g_ah);
    cudaGetSymbolAddress((void**)&al, g_al);
    cudaGetSymbolAddress((void**)&wh, g_wh);
    cudaGetSymbolAddress((void**)&wl, g_wl);

    constexpr int GEMM_SMEM = 65536;   // 4 x 16KB double-buffered tiles
    cudaFuncSetAttribute(mma_gemm<D_>, cudaFuncAttributeMaxDynamicSharedMemorySize, GEMM_SMEM);
    cudaFuncSetAttribute(mma_gemm<H_>, cudaFuncAttributeMaxDynamicSharedMemorySize, GEMM_SMEM);

    dim3 mgrid(MROWS / 128, H_ / 128);   // (512, 4)

    // ---- Layer 0: split-convert, HMMA input projection, scan ----
    conv_split<<<(H_ * D_) / 1024, 256>>>(Wih0, wh, wl);
    conv_split<<<((size_t)MROWS * D_) / 1024, 256>>>(x, ah, al);
    mma_gemm<D_><<<mgrid, 256, GEMM_SMEM>>>(ah, al, wh, wl, bih0, bhh0, xw);
    scan_kernel<true><<<128, 512>>>(xw, Whh0);

    // ---- Layer 1 ----
    conv_split<<<(H_ * H_) / 1024, 256>>>(Wih1, wh, wl);
    conv_split<<<((size_t)MROWS * H_) / 1024, 256>>>(xw, ah, al);
    mma_gemm<H_><<<mgrid, 256, GEMM_SMEM>>>(ah, al, wh, wl, bih1, bhh1, x2);
    scan_kernel<false><<<128, 512>>>(x2, Whh1);

    // ---- FC on final hidden state of layer 1 ----
    fc_kernel<<<B_, 256>>>(x2, Wfc, bfc, (float*)d_out);
}